// round 1
// baseline (speedup 1.0000x reference)
#include <cuda_runtime.h>
#include <math.h>

#define S_LEN 1024
#define D_MOD 1024
#define B_SZ 4
#define N_H 16
#define DH 64
#define MAXLEN 1024

// ---------------------------------------------------------------------------
// Scratch (device globals — no allocations allowed)
// ---------------------------------------------------------------------------
__device__ float g_pe[S_LEN * D_MOD];                       // 4 MB
__device__ float g_pos[S_LEN * 2 * D_MOD];                  // 8 MB
__device__ float g_xn[B_SZ * S_LEN * D_MOD];                // 16 MB
__device__ float g_tok[(size_t)B_SZ * S_LEN * 3 * D_MOD];   // 50 MB

// ---------------------------------------------------------------------------
// Sinusoidal positional encoding
// ---------------------------------------------------------------------------
__global__ void pe_kernel() {
    int s = blockIdx.x;
    for (int d = threadIdx.x; d < D_MOD; d += blockDim.x) {
        int i = d >> 1;
        float div = expf((float)(2 * i) * (-9.210340371976184f / (float)D_MOD));
        float ang = (float)s * div;
        g_pe[s * D_MOD + d] = (d & 1) ? cosf(ang) : sinf(ang);
    }
}

// ---------------------------------------------------------------------------
// NT SGEMM: C[M,N] = A[M,K] * B[N,K]^T   (both K-contiguous row-major)
// 64x64 tile, BK=16, 256 threads, 4x4 microtile
// ---------------------------------------------------------------------------
__global__ void __launch_bounds__(256) sgemm_nt(const float* __restrict__ A,
                                                const float* __restrict__ Bm,
                                                float* __restrict__ C,
                                                int M, int N, int K) {
    __shared__ float As[64][17];
    __shared__ float Bs[64][17];
    const int tx = threadIdx.x & 15, ty = threadIdx.x >> 4;
    const int m0 = blockIdx.y * 64, n0 = blockIdx.x * 64;
    const int lm = threadIdx.x >> 2, lk = (threadIdx.x & 3) * 4;

    float acc[4][4];
#pragma unroll
    for (int i = 0; i < 4; i++)
#pragma unroll
        for (int j = 0; j < 4; j++) acc[i][j] = 0.f;

    for (int k0 = 0; k0 < K; k0 += 16) {
        float4 a = *(const float4*)(A + (size_t)(m0 + lm) * K + k0 + lk);
        float4 b = *(const float4*)(Bm + (size_t)(n0 + lm) * K + k0 + lk);
        As[lm][lk] = a.x; As[lm][lk + 1] = a.y; As[lm][lk + 2] = a.z; As[lm][lk + 3] = a.w;
        Bs[lm][lk] = b.x; Bs[lm][lk + 1] = b.y; Bs[lm][lk + 2] = b.z; Bs[lm][lk + 3] = b.w;
        __syncthreads();
#pragma unroll
        for (int kk = 0; kk < 16; kk++) {
            float av[4], bv[4];
#pragma unroll
            for (int i = 0; i < 4; i++) av[i] = As[4 * ty + i][kk];
#pragma unroll
            for (int j = 0; j < 4; j++) bv[j] = Bs[4 * tx + j][kk];
#pragma unroll
            for (int i = 0; i < 4; i++)
#pragma unroll
                for (int j = 0; j < 4; j++) acc[i][j] = fmaf(av[i], bv[j], acc[i][j]);
        }
        __syncthreads();
    }
#pragma unroll
    for (int i = 0; i < 4; i++) {
        float4 o = make_float4(acc[i][0], acc[i][1], acc[i][2], acc[i][3]);
        *(float4*)(C + (size_t)(m0 + 4 * ty + i) * N + n0 + 4 * tx) = o;
    }
}

// ---------------------------------------------------------------------------
// LayerNorm: one block per row of D=1024, 256 threads
// ---------------------------------------------------------------------------
__global__ void __launch_bounds__(256) ln_kernel(const float* __restrict__ x,
                                                 const float* __restrict__ gamma,
                                                 const float* __restrict__ beta) {
    const int row = blockIdx.x;
    const float* xr = x + (size_t)row * D_MOD;
    float* xo = g_xn + (size_t)row * D_MOD;
    const int t = threadIdx.x;
    const int lane = t & 31, wid = t >> 5;
    __shared__ float red[8];

    float v[4];
    float s = 0.f;
#pragma unroll
    for (int i = 0; i < 4; i++) { v[i] = xr[t + i * 256]; s += v[i]; }
#pragma unroll
    for (int o = 16; o > 0; o >>= 1) s += __shfl_xor_sync(0xffffffffu, s, o);
    if (lane == 0) red[wid] = s;
    __syncthreads();
    float tot = 0.f;
#pragma unroll
    for (int i = 0; i < 8; i++) tot += red[i];
    float mean = tot * (1.f / 1024.f);

    float sq = 0.f;
#pragma unroll
    for (int i = 0; i < 4; i++) { float d = v[i] - mean; sq += d * d; }
#pragma unroll
    for (int o = 16; o > 0; o >>= 1) sq += __shfl_xor_sync(0xffffffffu, sq, o);
    __syncthreads();
    if (lane == 0) red[wid] = sq;
    __syncthreads();
    float tot2 = 0.f;
#pragma unroll
    for (int i = 0; i < 8; i++) tot2 += red[i];
    float rstd = rsqrtf(tot2 * (1.f / 1024.f) + 1e-5f);

#pragma unroll
    for (int i = 0; i < 4; i++) {
        int c = t + i * 256;
        xo[c] = (v[i] - mean) * rstd * gamma[c] + beta[c];
    }
}

// ---------------------------------------------------------------------------
// Flash attention: effective head dim 128 = [tok(64) ; pos(64)]
//   score = (q.k) * sqrt(128) + bias_table[k-q+1024, h]
// grid (S/64, H, B), 256 threads, 4x4 microtiles, online softmax
// ---------------------------------------------------------------------------
__global__ void __launch_bounds__(256, 1) flash_kernel(const float* __restrict__ bias_table,
                                                       float* __restrict__ out) {
    extern __shared__ float sm[];
    float* Qs = sm;               // [64][129]
    float* Ks = Qs + 64 * 129;    // [64][129]
    float* Vs = Ks + 64 * 129;    // [64][65]
    float* Ps = Vs + 64 * 65;     // [64][65]  Ps[k][q]
    float* bias_s = Ps + 64 * 65; // [128]

    const int b = blockIdx.z, h = blockIdx.y, q0 = blockIdx.x * 64;
    const int t = threadIdx.x, tx = t & 15, ty = t >> 4;
    const float* tokb = g_tok + (size_t)b * S_LEN * 3 * D_MOD;
    const int hc = h * 64;

    // Q tile: [q][d], d<64 = tok_q, d>=64 = pos_q
    for (int e = t; e < 64 * 128; e += 256) {
        int d = e & 127, q = e >> 7;
        float v = (d < 64) ? tokb[(size_t)(q0 + q) * 3072 + D_MOD + hc + d]
                           : g_pos[(q0 + q) * 2048 + D_MOD + hc + (d - 64)];
        Qs[q * 129 + d] = v;
    }

    float m_i[4], l_i[4], O[4][4];
#pragma unroll
    for (int i = 0; i < 4; i++) {
        m_i[i] = -INFINITY; l_i[i] = 0.f;
#pragma unroll
        for (int j = 0; j < 4; j++) O[i][j] = 0.f;
    }

    const float SCALE = 11.313708498984761f;  // sqrt(2*dh) = sqrt(128)
    const float LOG2E = 1.4426950408889634f;

    for (int k0 = 0; k0 < S_LEN; k0 += 64) {
        __syncthreads();  // previous PV finished before overwriting K/V
        for (int e = t; e < 64 * 128; e += 256) {
            int d = e & 127, k = e >> 7;
            float v = (d < 64) ? tokb[(size_t)(k0 + k) * 3072 + hc + d]
                               : g_pos[(k0 + k) * 2048 + hc + (d - 64)];
            Ks[k * 129 + d] = v;
        }
        for (int e = t; e < 64 * 64; e += 256) {
            int d = e & 63, k = e >> 6;
            Vs[k * 65 + d] = tokb[(size_t)(k0 + k) * 3072 + 2 * D_MOD + hc + d];
        }
        if (t < 128) {
            int rel = k0 - q0 + MAXLEN - 63 + t;  // idx 63+kl-ql in [0,126]
            bias_s[t] = (rel >= 0 && rel < 2 * MAXLEN) ? bias_table[rel * N_H + h] : 0.f;
        }
        __syncthreads();

        // S tile = Q K^T over de=128
        float acc[4][4];
#pragma unroll
        for (int i = 0; i < 4; i++)
#pragma unroll
            for (int j = 0; j < 4; j++) acc[i][j] = 0.f;

#pragma unroll 4
        for (int d = 0; d < 128; d++) {
            float qv[4], kv[4];
#pragma unroll
            for (int i = 0; i < 4; i++) qv[i] = Qs[(4 * ty + i) * 129 + d];
#pragma unroll
            for (int j = 0; j < 4; j++) kv[j] = Ks[(4 * tx + j) * 129 + d];
#pragma unroll
            for (int i = 0; i < 4; i++)
#pragma unroll
                for (int j = 0; j < 4; j++) acc[i][j] = fmaf(qv[i], kv[j], acc[i][j]);
        }

        // scale + relative bias
#pragma unroll
        for (int i = 0; i < 4; i++)
#pragma unroll
            for (int j = 0; j < 4; j++) {
                int idx = 63 + (4 * tx + j) - (4 * ty + i);
                acc[i][j] = acc[i][j] * SCALE + bias_s[idx];
            }

        // online softmax update (row stats reduced over the 16 tx lanes)
#pragma unroll
        for (int i = 0; i < 4; i++) {
            float m = fmaxf(fmaxf(acc[i][0], acc[i][1]), fmaxf(acc[i][2], acc[i][3]));
#pragma unroll
            for (int o = 1; o < 16; o <<= 1) m = fmaxf(m, __shfl_xor_sync(0xffffffffu, m, o));
            float mn = fmaxf(m_i[i], m);
            float alpha = exp2f((m_i[i] - mn) * LOG2E);
            m_i[i] = mn;
            float r = 0.f;
#pragma unroll
            for (int j = 0; j < 4; j++) {
                float p = exp2f((acc[i][j] - mn) * LOG2E);
                acc[i][j] = p;
                r += p;
            }
#pragma unroll
            for (int o = 1; o < 16; o <<= 1) r += __shfl_xor_sync(0xffffffffu, r, o);
            l_i[i] = l_i[i] * alpha + r;
#pragma unroll
            for (int j = 0; j < 4; j++) O[i][j] *= alpha;
        }

        // stage P (transposed) for the PV product
#pragma unroll
        for (int i = 0; i < 4; i++)
#pragma unroll
            for (int j = 0; j < 4; j++)
                Ps[(4 * tx + j) * 65 + (4 * ty + i)] = acc[i][j];
        __syncthreads();

        // O += P V
#pragma unroll 4
        for (int k = 0; k < 64; k++) {
            float pv[4], vv[4];
#pragma unroll
            for (int i = 0; i < 4; i++) pv[i] = Ps[k * 65 + 4 * ty + i];
#pragma unroll
            for (int j = 0; j < 4; j++) vv[j] = Vs[k * 65 + 4 * tx + j];
#pragma unroll
            for (int i = 0; i < 4; i++)
#pragma unroll
                for (int j = 0; j < 4; j++) O[i][j] = fmaf(pv[i], vv[j], O[i][j]);
        }
    }

    // epilogue: normalize and store (B,S,D) with col = h*64 + d
#pragma unroll
    for (int i = 0; i < 4; i++) {
        float inv = 1.f / l_i[i];
        float4 o4 = make_float4(O[i][0] * inv, O[i][1] * inv, O[i][2] * inv, O[i][3] * inv);
        *(float4*)(out + ((size_t)b * S_LEN + q0 + 4 * ty + i) * D_MOD + hc + 4 * tx) = o4;
    }
}

// ---------------------------------------------------------------------------
// Launch
// ---------------------------------------------------------------------------
extern "C" void kernel_launch(void* const* d_in, const int* in_sizes, int n_in,
                              void* d_out, int out_size) {
    const float* x          = (const float*)d_in[0];
    const float* gamma      = (const float*)d_in[1];
    const float* beta       = (const float*)d_in[2];
    const float* w_pos      = (const float*)d_in[3];
    const float* w_tok      = (const float*)d_in[4];
    const float* bias_table = (const float*)d_in[5];
    float* out = (float*)d_out;

    float *pe, *pos, *xn, *tok;
    cudaGetSymbolAddress((void**)&pe, g_pe);
    cudaGetSymbolAddress((void**)&pos, g_pos);
    cudaGetSymbolAddress((void**)&xn, g_xn);
    cudaGetSymbolAddress((void**)&tok, g_tok);

    // 1. positional encoding
    pe_kernel<<<S_LEN, 256>>>();
    // 2. pos = pe @ w_pos.T  (1024 x 2048, K=1024)
    sgemm_nt<<<dim3(2 * D_MOD / 64, S_LEN / 64), 256>>>(pe, w_pos, pos, S_LEN, 2 * D_MOD, D_MOD);
    // 3. layernorm
    ln_kernel<<<B_SZ * S_LEN, 256>>>(x, gamma, beta);
    // 4. tok = xn @ w_tok.T  (4096 x 3072, K=1024)
    sgemm_nt<<<dim3(3 * D_MOD / 64, B_SZ * S_LEN / 64), 256>>>(xn, w_tok, tok, B_SZ * S_LEN, 3 * D_MOD, D_MOD);
    // 5. fused TUPE flash attention
    int smem = (64 * 129 * 2 + 64 * 65 * 2 + 128) * (int)sizeof(float);  // 99,840 B
    cudaFuncSetAttribute(flash_kernel, cudaFuncAttributeMaxDynamicSharedMemorySize, smem);
    flash_kernel<<<dim3(S_LEN / 64, N_H, B_SZ), 256, smem>>>(bias_table, out);
}

// round 3
// speedup vs baseline: 1.4265x; 1.4265x over previous
#include <cuda_runtime.h>
#include <cuda_fp16.h>
#include <math.h>
#include <stdint.h>

#define S_LEN 1024
#define D_MOD 1024
#define B_SZ 4
#define N_H 16
#define MAXLEN 1024

// ---------------------------------------------------------------------------
// Scratch (device globals — no allocations allowed)
// ---------------------------------------------------------------------------
__device__ float g_pos[S_LEN * 2 * D_MOD];                    // 8 MB
__device__ float g_tok[(size_t)B_SZ * S_LEN * 3 * D_MOD];     // 50 MB
__device__ __half g_pe_hi[S_LEN * D_MOD],       g_pe_lo[S_LEN * D_MOD];
__device__ __half g_wpos_hi[2 * D_MOD * D_MOD], g_wpos_lo[2 * D_MOD * D_MOD];
__device__ __half g_xn_hi[B_SZ * S_LEN * D_MOD], g_xn_lo[B_SZ * S_LEN * D_MOD];
__device__ __half g_wtok_hi[3 * D_MOD * D_MOD], g_wtok_lo[3 * D_MOD * D_MOD];

// ---------------------------------------------------------------------------
// helpers
// ---------------------------------------------------------------------------
__device__ __forceinline__ uint32_t smem_u32(const void* p) {
    uint32_t a;
    asm("{ .reg .u64 t; cvta.to.shared.u64 t, %1; cvt.u32.u64 %0, t; }" : "=r"(a) : "l"(p));
    return a;
}

__device__ __forceinline__ void cp_async16(uint32_t dst, const void* src) {
    asm volatile("cp.async.cg.shared.global [%0], [%1], 16;" :: "r"(dst), "l"(src) : "memory");
}

__device__ __forceinline__ void ldm_x4(uint32_t* r, uint32_t addr) {
    asm volatile("ldmatrix.sync.aligned.m8n8.x4.shared.b16 {%0,%1,%2,%3}, [%4];"
                 : "=r"(r[0]), "=r"(r[1]), "=r"(r[2]), "=r"(r[3]) : "r"(addr));
}

__device__ __forceinline__ void mma_f16(float* c, const uint32_t* a, const uint32_t* b) {
    asm volatile("mma.sync.aligned.m16n8k16.row.col.f32.f16.f16.f32 "
                 "{%0,%1,%2,%3}, {%4,%5,%6,%7}, {%8,%9}, {%0,%1,%2,%3};"
                 : "+f"(c[0]), "+f"(c[1]), "+f"(c[2]), "+f"(c[3])
                 : "r"(a[0]), "r"(a[1]), "r"(a[2]), "r"(a[3]), "r"(b[0]), "r"(b[1]));
}

// ---------------------------------------------------------------------------
// PE (sinusoidal) -> fp16 hi/lo split
// ---------------------------------------------------------------------------
__global__ void pe_kernel() {
    int s = blockIdx.x;
    for (int d = threadIdx.x; d < D_MOD; d += blockDim.x) {
        int i = d >> 1;
        float div = expf((float)(2 * i) * (-9.210340371976184f / (float)D_MOD));
        float ang = (float)s * div;
        float v = (d & 1) ? cosf(ang) : sinf(ang);
        __half h = __float2half_rn(v);
        g_pe_hi[s * D_MOD + d] = h;
        g_pe_lo[s * D_MOD + d] = __float2half_rn(v - __half2float(h));
    }
}

// fp32 -> fp16 hi/lo split for weights
__global__ void split_kernel(const float* __restrict__ src, __half* __restrict__ hi,
                             __half* __restrict__ lo, int n) {
    int i = blockIdx.x * blockDim.x + threadIdx.x;
    if (i < n) {
        float x = src[i];
        __half h = __float2half_rn(x);
        hi[i] = h;
        lo[i] = __float2half_rn(x - __half2float(h));
    }
}

// ---------------------------------------------------------------------------
// LayerNorm -> fp16 hi/lo split
// ---------------------------------------------------------------------------
__global__ void __launch_bounds__(256) ln_kernel(const float* __restrict__ x,
                                                 const float* __restrict__ gamma,
                                                 const float* __restrict__ beta) {
    const int row = blockIdx.x;
    const float* xr = x + (size_t)row * D_MOD;
    const int t = threadIdx.x;
    const int lane = t & 31, wid = t >> 5;
    __shared__ float red[8];

    float v[4];
    float s = 0.f;
#pragma unroll
    for (int i = 0; i < 4; i++) { v[i] = xr[t + i * 256]; s += v[i]; }
#pragma unroll
    for (int o = 16; o > 0; o >>= 1) s += __shfl_xor_sync(0xffffffffu, s, o);
    if (lane == 0) red[wid] = s;
    __syncthreads();
    float tot = 0.f;
#pragma unroll
    for (int i = 0; i < 8; i++) tot += red[i];
    float mean = tot * (1.f / 1024.f);

    float sq = 0.f;
#pragma unroll
    for (int i = 0; i < 4; i++) { float d = v[i] - mean; sq += d * d; }
#pragma unroll
    for (int o = 16; o > 0; o >>= 1) sq += __shfl_xor_sync(0xffffffffu, sq, o);
    __syncthreads();
    if (lane == 0) red[wid] = sq;
    __syncthreads();
    float tot2 = 0.f;
#pragma unroll
    for (int i = 0; i < 8; i++) tot2 += red[i];
    float rstd = rsqrtf(tot2 * (1.f / 1024.f) + 1e-5f);

#pragma unroll
    for (int i = 0; i < 4; i++) {
        int c = t + i * 256;
        float y = (v[i] - mean) * rstd * gamma[c] + beta[c];
        __half h = __float2half_rn(y);
        g_xn_hi[(size_t)row * D_MOD + c] = h;
        g_xn_lo[(size_t)row * D_MOD + c] = __float2half_rn(y - __half2float(h));
    }
}

// ---------------------------------------------------------------------------
// mma.sync fp16x2-split NT GEMM: C[M,N] = A[M,K] * B[N,K]^T
// 128x128 tile, BK=32, 8 warps (2m x 4n of 64x32), cp.async double buffer
// smem per operand buffer: 128 rows x 40 halves (pad 32->40) = 10240 B
// ---------------------------------------------------------------------------
#define OPBUF 10240
#define GEMM_SMEM (8 * OPBUF)   // 2 stages x 4 operands = 81920 B

__global__ void __launch_bounds__(256) gemm_f16x2(
    const __half* __restrict__ Ahi, const __half* __restrict__ Alo,
    const __half* __restrict__ Bhi, const __half* __restrict__ Blo,
    float* __restrict__ C, int M, int N, int K)
{
    extern __shared__ char sm[];
    const uint32_t sb = smem_u32(sm);
    const int tid = threadIdx.x;
    const int lane = tid & 31, wid = tid >> 5;
    const int wm = wid >> 2, wn = wid & 3;          // warp tile 64m x 32n
    const int m0 = blockIdx.y * 128, n0 = blockIdx.x * 128;

    float acc[4][4][4];
#pragma unroll
    for (int i = 0; i < 4; i++)
#pragma unroll
        for (int j = 0; j < 4; j++)
#pragma unroll
            for (int r = 0; r < 4; r++) acc[i][j][r] = 0.f;

    const __half* srcs[4] = {Ahi, Alo, Bhi, Blo};
    const int rows0[4] = {m0, m0, n0, n0};

    const int NCH = K >> 5;  // 32

    // ldmatrix address components (per lane)
    const int lj = lane >> 3, lr = lane & 7;

    // prefetch chunk 0 into stage 0
#pragma unroll
    for (int op = 0; op < 4; op++)
#pragma unroll
        for (int it = 0; it < 2; it++) {
            int e = tid + (it << 8);
            int r = e >> 2, cs = e & 3;
            cp_async16(sb + op * OPBUF + r * 80 + cs * 16,
                       srcs[op] + (size_t)(rows0[op] + r) * K + (cs << 3));
        }
    asm volatile("cp.async.commit_group;" ::: "memory");

    for (int i = 0; i < NCH; i++) {
        const int s = i & 1;
        if (i + 1 < NCH) {
            const int s2 = s ^ 1, k0 = (i + 1) << 5;
#pragma unroll
            for (int op = 0; op < 4; op++)
#pragma unroll
                for (int it = 0; it < 2; it++) {
                    int e = tid + (it << 8);
                    int r = e >> 2, cs = e & 3;
                    cp_async16(sb + (s2 * 4 + op) * OPBUF + r * 80 + cs * 16,
                               srcs[op] + (size_t)(rows0[op] + r) * K + k0 + (cs << 3));
                }
            asm volatile("cp.async.commit_group;" ::: "memory");
            asm volatile("cp.async.wait_group 1;" ::: "memory");
        } else {
            asm volatile("cp.async.wait_group 0;" ::: "memory");
        }
        __syncthreads();

        const uint32_t ah_b = sb + (s * 4 + 0) * OPBUF;
        const uint32_t al_b = sb + (s * 4 + 1) * OPBUF;
        const uint32_t bh_b = sb + (s * 4 + 2) * OPBUF;
        const uint32_t bl_b = sb + (s * 4 + 3) * OPBUF;

#pragma unroll
        for (int kk = 0; kk < 32; kk += 16) {
            // A fragments: 4 m16 tiles, hi & lo
            uint32_t ah[4][4], al[4][4];
#pragma unroll
            for (int tm = 0; tm < 4; tm++) {
                int m = wm * 64 + tm * 16 + (lj & 1) * 8 + lr;
                int k = kk + (lj >> 1) * 8;
                ldm_x4(ah[tm], ah_b + m * 80 + k * 2);
                ldm_x4(al[tm], al_b + m * 80 + k * 2);
            }
            // B fragments: 2 n16 pairs -> 4 n8 tiles, hi & lo
            uint32_t bh[2][4], bl[2][4];
#pragma unroll
            for (int tn = 0; tn < 2; tn++) {
                int n = wn * 32 + tn * 16 + (lj >> 1) * 8 + lr;
                int k = kk + (lj & 1) * 8;
                ldm_x4(bh[tn], bh_b + n * 80 + k * 2);
                ldm_x4(bl[tn], bl_b + n * 80 + k * 2);
            }
#pragma unroll
            for (int tm = 0; tm < 4; tm++)
#pragma unroll
                for (int t8 = 0; t8 < 4; t8++) {
                    uint32_t bhr[2] = {bh[t8 >> 1][2 * (t8 & 1)], bh[t8 >> 1][2 * (t8 & 1) + 1]};
                    uint32_t blr[2] = {bl[t8 >> 1][2 * (t8 & 1)], bl[t8 >> 1][2 * (t8 & 1) + 1]};
                    mma_f16(acc[tm][t8], ah[tm], bhr);
                    mma_f16(acc[tm][t8], ah[tm], blr);
                    mma_f16(acc[tm][t8], al[tm], bhr);
                }
        }
        __syncthreads();
    }

    // epilogue: c0,c1 -> (m, n..n+1), c2,c3 -> (m+8, n..n+1)
#pragma unroll
    for (int tm = 0; tm < 4; tm++) {
        int m = m0 + wm * 64 + tm * 16 + (lane >> 2);
#pragma unroll
        for (int t8 = 0; t8 < 4; t8++) {
            int n = n0 + wn * 32 + t8 * 8 + 2 * (lane & 3);
            *(float2*)(C + (size_t)m * N + n) = make_float2(acc[tm][t8][0], acc[tm][t8][1]);
            *(float2*)(C + (size_t)(m + 8) * N + n) = make_float2(acc[tm][t8][2], acc[tm][t8][3]);
        }
    }
}

// ---------------------------------------------------------------------------
// Flash attention: effective head dim 128 = [tok(64) ; pos(64)]
//   score = (q.k) * sqrt(128) + bias_table[k-q+1024, h]
// ---------------------------------------------------------------------------
__global__ void __launch_bounds__(256, 1) flash_kernel(const float* __restrict__ bias_table,
                                                       float* __restrict__ out) {
    extern __shared__ float smf[];
    float* Qs = smf;               // [64][129]
    float* Ks = Qs + 64 * 129;     // [64][129]
    float* Vs = Ks + 64 * 129;     // [64][65]
    float* Ps = Vs + 64 * 65;      // [64][65]
    float* bias_s = Ps + 64 * 65;  // [128]

    const int b = blockIdx.z, h = blockIdx.y, q0 = blockIdx.x * 64;
    const int t = threadIdx.x, tx = t & 15, ty = t >> 4;
    const float* tokb = g_tok + (size_t)b * S_LEN * 3 * D_MOD;
    const int hc = h * 64;

    for (int e = t; e < 64 * 128; e += 256) {
        int d = e & 127, q = e >> 7;
        float v = (d < 64) ? tokb[(size_t)(q0 + q) * 3072 + D_MOD + hc + d]
                           : g_pos[(q0 + q) * 2048 + D_MOD + hc + (d - 64)];
        Qs[q * 129 + d] = v;
    }

    float m_i[4], l_i[4], O[4][4];
#pragma unroll
    for (int i = 0; i < 4; i++) {
        m_i[i] = -INFINITY; l_i[i] = 0.f;
#pragma unroll
        for (int j = 0; j < 4; j++) O[i][j] = 0.f;
    }

    const float SCALE = 11.313708498984761f;
    const float LOG2E = 1.4426950408889634f;

    for (int k0 = 0; k0 < S_LEN; k0 += 64) {
        __syncthreads();
        for (int e = t; e < 64 * 128; e += 256) {
            int d = e & 127, k = e >> 7;
            float v = (d < 64) ? tokb[(size_t)(k0 + k) * 3072 + hc + d]
                               : g_pos[(k0 + k) * 2048 + hc + (d - 64)];
            Ks[k * 129 + d] = v;
        }
        for (int e = t; e < 64 * 64; e += 256) {
            int d = e & 63, k = e >> 6;
            Vs[k * 65 + d] = tokb[(size_t)(k0 + k) * 3072 + 2 * D_MOD + hc + d];
        }
        if (t < 128) {
            int rel = k0 - q0 + MAXLEN - 63 + t;
            bias_s[t] = (rel >= 0 && rel < 2 * MAXLEN) ? bias_table[rel * N_H + h] : 0.f;
        }
        __syncthreads();

        float acc[4][4];
#pragma unroll
        for (int i = 0; i < 4; i++)
#pragma unroll
            for (int j = 0; j < 4; j++) acc[i][j] = 0.f;

#pragma unroll 4
        for (int d = 0; d < 128; d++) {
            float qv[4], kv[4];
#pragma unroll
            for (int i = 0; i < 4; i++) qv[i] = Qs[(4 * ty + i) * 129 + d];
#pragma unroll
            for (int j = 0; j < 4; j++) kv[j] = Ks[(4 * tx + j) * 129 + d];
#pragma unroll
            for (int i = 0; i < 4; i++)
#pragma unroll
                for (int j = 0; j < 4; j++) acc[i][j] = fmaf(qv[i], kv[j], acc[i][j]);
        }

#pragma unroll
        for (int i = 0; i < 4; i++)
#pragma unroll
            for (int j = 0; j < 4; j++) {
                int idx = 63 + (4 * tx + j) - (4 * ty + i);
                acc[i][j] = acc[i][j] * SCALE + bias_s[idx];
            }

#pragma unroll
        for (int i = 0; i < 4; i++) {
            float m = fmaxf(fmaxf(acc[i][0], acc[i][1]), fmaxf(acc[i][2], acc[i][3]));
#pragma unroll
            for (int o = 1; o < 16; o <<= 1) m = fmaxf(m, __shfl_xor_sync(0xffffffffu, m, o));
            float mn = fmaxf(m_i[i], m);
            float alpha = exp2f((m_i[i] - mn) * LOG2E);
            m_i[i] = mn;
            float r = 0.f;
#pragma unroll
            for (int j = 0; j < 4; j++) {
                float p = exp2f((acc[i][j] - mn) * LOG2E);
                acc[i][j] = p;
                r += p;
            }
#pragma unroll
            for (int o = 1; o < 16; o <<= 1) r += __shfl_xor_sync(0xffffffffu, r, o);
            l_i[i] = l_i[i] * alpha + r;
#pragma unroll
            for (int j = 0; j < 4; j++) O[i][j] *= alpha;
        }

#pragma unroll
        for (int i = 0; i < 4; i++)
#pragma unroll
            for (int j = 0; j < 4; j++)
                Ps[(4 * tx + j) * 65 + (4 * ty + i)] = acc[i][j];
        __syncthreads();

#pragma unroll 4
        for (int k = 0; k < 64; k++) {
            float pv[4], vv[4];
#pragma unroll
            for (int i = 0; i < 4; i++) pv[i] = Ps[k * 65 + 4 * ty + i];
#pragma unroll
            for (int j = 0; j < 4; j++) vv[j] = Vs[k * 65 + 4 * tx + j];
#pragma unroll
            for (int i = 0; i < 4; i++)
#pragma unroll
                for (int j = 0; j < 4; j++) O[i][j] = fmaf(pv[i], vv[j], O[i][j]);
        }
    }

#pragma unroll
    for (int i = 0; i < 4; i++) {
        float inv = 1.f / l_i[i];
        float4 o4 = make_float4(O[i][0] * inv, O[i][1] * inv, O[i][2] * inv, O[i][3] * inv);
        *(float4*)(out + ((size_t)b * S_LEN + q0 + 4 * ty + i) * D_MOD + hc + 4 * tx) = o4;
    }
}

// ---------------------------------------------------------------------------
// Launch
// ---------------------------------------------------------------------------
extern "C" void kernel_launch(void* const* d_in, const int* in_sizes, int n_in,
                              void* d_out, int out_size) {
    const float* x          = (const float*)d_in[0];
    const float* gamma      = (const float*)d_in[1];
    const float* beta       = (const float*)d_in[2];
    const float* w_pos      = (const float*)d_in[3];
    const float* w_tok      = (const float*)d_in[4];
    const float* bias_table = (const float*)d_in[5];
    float* out = (float*)d_out;

    float *pos, *tok;
    __half *pe_hi, *pe_lo, *wpos_hi, *wpos_lo, *xn_hi, *xn_lo, *wtok_hi, *wtok_lo;
    cudaGetSymbolAddress((void**)&pos, g_pos);
    cudaGetSymbolAddress((void**)&tok, g_tok);
    cudaGetSymbolAddress((void**)&pe_hi, g_pe_hi);
    cudaGetSymbolAddress((void**)&pe_lo, g_pe_lo);
    cudaGetSymbolAddress((void**)&wpos_hi, g_wpos_hi);
    cudaGetSymbolAddress((void**)&wpos_lo, g_wpos_lo);
    cudaGetSymbolAddress((void**)&xn_hi, g_xn_hi);
    cudaGetSymbolAddress((void**)&xn_lo, g_xn_lo);
    cudaGetSymbolAddress((void**)&wtok_hi, g_wtok_hi);
    cudaGetSymbolAddress((void**)&wtok_lo, g_wtok_lo);

    cudaFuncSetAttribute(gemm_f16x2, cudaFuncAttributeMaxDynamicSharedMemorySize, GEMM_SMEM);
    int fsmem = (64 * 129 * 2 + 64 * 65 * 2 + 128) * (int)sizeof(float);
    cudaFuncSetAttribute(flash_kernel, cudaFuncAttributeMaxDynamicSharedMemorySize, fsmem);

    // 1. positional encoding (fp16 hi/lo)
    pe_kernel<<<S_LEN, 256>>>();
    // 2. weight splits
    split_kernel<<<(2 * D_MOD * D_MOD + 255) / 256, 256>>>(w_pos, wpos_hi, wpos_lo, 2 * D_MOD * D_MOD);
    split_kernel<<<(3 * D_MOD * D_MOD + 255) / 256, 256>>>(w_tok, wtok_hi, wtok_lo, 3 * D_MOD * D_MOD);
    // 3. layernorm (fp16 hi/lo)
    ln_kernel<<<B_SZ * S_LEN, 256>>>(x, gamma, beta);
    // 4. pos = pe @ w_pos.T  (M=1024, N=2048, K=1024) — tensor cores
    gemm_f16x2<<<dim3(2 * D_MOD / 128, S_LEN / 128), 256, GEMM_SMEM>>>(
        pe_hi, pe_lo, wpos_hi, wpos_lo, pos, S_LEN, 2 * D_MOD, D_MOD);
    // 5. tok = xn @ w_tok.T  (M=4096, N=3072, K=1024) — tensor cores
    gemm_f16x2<<<dim3(3 * D_MOD / 128, B_SZ * S_LEN / 128), 256, GEMM_SMEM>>>(
        xn_hi, xn_lo, wtok_hi, wtok_lo, tok, B_SZ * S_LEN, 3 * D_MOD, D_MOD);
    // 6. fused TUPE flash attention
    flash_kernel<<<dim3(S_LEN / 64, N_H, B_SZ), 256, fsmem>>>(bias_table, out);
}

// round 4
// speedup vs baseline: 3.2496x; 2.2780x over previous
#include <cuda_runtime.h>
#include <cuda_fp16.h>
#include <math.h>
#include <stdint.h>

#define S_LEN 1024
#define D_MOD 1024
#define B_SZ 4
#define N_H 16
#define MAXLEN 1024

// ---------------------------------------------------------------------------
// Scratch (device globals — no allocations allowed)
// ---------------------------------------------------------------------------
__device__ __half g_pe_hi[S_LEN * D_MOD],        g_pe_lo[S_LEN * D_MOD];
__device__ __half g_wpos_hi[2 * D_MOD * D_MOD],  g_wpos_lo[2 * D_MOD * D_MOD];
__device__ __half g_xn_hi[B_SZ * S_LEN * D_MOD], g_xn_lo[B_SZ * S_LEN * D_MOD];
__device__ __half g_wtok_hi[3 * D_MOD * D_MOD],  g_wtok_lo[3 * D_MOD * D_MOD];
// GEMM outputs (fp16 hi/lo) — consumed only by flash attention
__device__ __half g_ph[S_LEN * 2 * D_MOD], g_pl[S_LEN * 2 * D_MOD];                     // pos
__device__ __half g_th[(size_t)B_SZ * S_LEN * 3 * D_MOD], g_tl[(size_t)B_SZ * S_LEN * 3 * D_MOD]; // tok

// ---------------------------------------------------------------------------
// helpers
// ---------------------------------------------------------------------------
__device__ __forceinline__ uint32_t smem_u32(const void* p) {
    uint32_t a;
    asm("{ .reg .u64 t; cvta.to.shared.u64 t, %1; cvt.u32.u64 %0, t; }" : "=r"(a) : "l"(p));
    return a;
}
__device__ __forceinline__ void cp_async16(uint32_t dst, const void* src) {
    asm volatile("cp.async.cg.shared.global [%0], [%1], 16;" :: "r"(dst), "l"(src) : "memory");
}
__device__ __forceinline__ void cp_async4(uint32_t dst, const void* src) {
    asm volatile("cp.async.ca.shared.global [%0], [%1], 4;" :: "r"(dst), "l"(src) : "memory");
}
#define CP_COMMIT() asm volatile("cp.async.commit_group;" ::: "memory")
#define CP_WAIT(n)  asm volatile("cp.async.wait_group %0;" :: "n"(n) : "memory")

__device__ __forceinline__ void ldm_x4(uint32_t* r, uint32_t addr) {
    asm volatile("ldmatrix.sync.aligned.m8n8.x4.shared.b16 {%0,%1,%2,%3}, [%4];"
                 : "=r"(r[0]), "=r"(r[1]), "=r"(r[2]), "=r"(r[3]) : "r"(addr));
}
__device__ __forceinline__ void ldm_x4t(uint32_t* r, uint32_t addr) {
    asm volatile("ldmatrix.sync.aligned.m8n8.x4.trans.shared.b16 {%0,%1,%2,%3}, [%4];"
                 : "=r"(r[0]), "=r"(r[1]), "=r"(r[2]), "=r"(r[3]) : "r"(addr));
}
__device__ __forceinline__ void mma_f16(float* c, const uint32_t* a, const uint32_t* b) {
    asm volatile("mma.sync.aligned.m16n8k16.row.col.f32.f16.f16.f32 "
                 "{%0,%1,%2,%3}, {%4,%5,%6,%7}, {%8,%9}, {%0,%1,%2,%3};"
                 : "+f"(c[0]), "+f"(c[1]), "+f"(c[2]), "+f"(c[3])
                 : "r"(a[0]), "r"(a[1]), "r"(a[2]), "r"(a[3]), "r"(b[0]), "r"(b[1]));
}
__device__ __forceinline__ uint32_t h2u(__half2 h) { return *reinterpret_cast<uint32_t*>(&h); }

// ---------------------------------------------------------------------------
// PE (sinusoidal) -> fp16 hi/lo split
// ---------------------------------------------------------------------------
__global__ void pe_kernel() {
    int s = blockIdx.x;
    for (int d = threadIdx.x; d < D_MOD; d += blockDim.x) {
        int i = d >> 1;
        float div = expf((float)(2 * i) * (-9.210340371976184f / (float)D_MOD));
        float ang = (float)s * div;
        float v = (d & 1) ? cosf(ang) : sinf(ang);
        __half h = __float2half_rn(v);
        g_pe_hi[s * D_MOD + d] = h;
        g_pe_lo[s * D_MOD + d] = __float2half_rn(v - __half2float(h));
    }
}

__global__ void split_kernel(const float* __restrict__ src, __half* __restrict__ hi,
                             __half* __restrict__ lo, int n) {
    int i = blockIdx.x * blockDim.x + threadIdx.x;
    if (i < n) {
        float x = src[i];
        __half h = __float2half_rn(x);
        hi[i] = h;
        lo[i] = __float2half_rn(x - __half2float(h));
    }
}

// ---------------------------------------------------------------------------
// LayerNorm -> fp16 hi/lo split
// ---------------------------------------------------------------------------
__global__ void __launch_bounds__(256) ln_kernel(const float* __restrict__ x,
                                                 const float* __restrict__ gamma,
                                                 const float* __restrict__ beta) {
    const int row = blockIdx.x;
    const float* xr = x + (size_t)row * D_MOD;
    const int t = threadIdx.x;
    const int lane = t & 31, wid = t >> 5;
    __shared__ float red[8];

    float v[4];
    float s = 0.f;
#pragma unroll
    for (int i = 0; i < 4; i++) { v[i] = xr[t + i * 256]; s += v[i]; }
#pragma unroll
    for (int o = 16; o > 0; o >>= 1) s += __shfl_xor_sync(0xffffffffu, s, o);
    if (lane == 0) red[wid] = s;
    __syncthreads();
    float tot = 0.f;
#pragma unroll
    for (int i = 0; i < 8; i++) tot += red[i];
    float mean = tot * (1.f / 1024.f);

    float sq = 0.f;
#pragma unroll
    for (int i = 0; i < 4; i++) { float d = v[i] - mean; sq += d * d; }
#pragma unroll
    for (int o = 16; o > 0; o >>= 1) sq += __shfl_xor_sync(0xffffffffu, sq, o);
    __syncthreads();
    if (lane == 0) red[wid] = sq;
    __syncthreads();
    float tot2 = 0.f;
#pragma unroll
    for (int i = 0; i < 8; i++) tot2 += red[i];
    float rstd = rsqrtf(tot2 * (1.f / 1024.f) + 1e-5f);

#pragma unroll
    for (int i = 0; i < 4; i++) {
        int c = t + i * 256;
        float y = (v[i] - mean) * rstd * gamma[c] + beta[c];
        __half h = __float2half_rn(y);
        g_xn_hi[(size_t)row * D_MOD + c] = h;
        g_xn_lo[(size_t)row * D_MOD + c] = __float2half_rn(y - __half2float(h));
    }
}

// ---------------------------------------------------------------------------
// mma.sync fp16x2-split NT GEMM: C = A[M,K] * B[N,K]^T, fp16 hi/lo output
// ---------------------------------------------------------------------------
#define OPBUF 10240
#define GEMM_SMEM (8 * OPBUF)

__global__ void __launch_bounds__(256) gemm_f16x2(
    const __half* __restrict__ Ahi, const __half* __restrict__ Alo,
    const __half* __restrict__ Bhi, const __half* __restrict__ Blo,
    __half* __restrict__ Chi, __half* __restrict__ Clo, int M, int N, int K)
{
    extern __shared__ char sm[];
    const uint32_t sb = smem_u32(sm);
    const int tid = threadIdx.x;
    const int lane = tid & 31, wid = tid >> 5;
    const int wm = wid >> 2, wn = wid & 3;
    const int m0 = blockIdx.y * 128, n0 = blockIdx.x * 128;

    float acc[4][4][4];
#pragma unroll
    for (int i = 0; i < 4; i++)
#pragma unroll
        for (int j = 0; j < 4; j++)
#pragma unroll
            for (int r = 0; r < 4; r++) acc[i][j][r] = 0.f;

    const __half* srcs[4] = {Ahi, Alo, Bhi, Blo};
    const int rows0[4] = {m0, m0, n0, n0};
    const int NCH = K >> 5;
    const int lj = lane >> 3, lr = lane & 7;

#pragma unroll
    for (int op = 0; op < 4; op++)
#pragma unroll
        for (int it = 0; it < 2; it++) {
            int e = tid + (it << 8);
            int r = e >> 2, cs = e & 3;
            cp_async16(sb + op * OPBUF + r * 80 + cs * 16,
                       srcs[op] + (size_t)(rows0[op] + r) * K + (cs << 3));
        }
    CP_COMMIT();

    for (int i = 0; i < NCH; i++) {
        const int s = i & 1;
        if (i + 1 < NCH) {
            const int s2 = s ^ 1, k0 = (i + 1) << 5;
#pragma unroll
            for (int op = 0; op < 4; op++)
#pragma unroll
                for (int it = 0; it < 2; it++) {
                    int e = tid + (it << 8);
                    int r = e >> 2, cs = e & 3;
                    cp_async16(sb + (s2 * 4 + op) * OPBUF + r * 80 + cs * 16,
                               srcs[op] + (size_t)(rows0[op] + r) * K + k0 + (cs << 3));
                }
            CP_COMMIT();
            CP_WAIT(1);
        } else {
            CP_WAIT(0);
        }
        __syncthreads();

        const uint32_t ah_b = sb + (s * 4 + 0) * OPBUF;
        const uint32_t al_b = sb + (s * 4 + 1) * OPBUF;
        const uint32_t bh_b = sb + (s * 4 + 2) * OPBUF;
        const uint32_t bl_b = sb + (s * 4 + 3) * OPBUF;

#pragma unroll
        for (int kk = 0; kk < 32; kk += 16) {
            uint32_t ah[4][4], al[4][4];
#pragma unroll
            for (int tm = 0; tm < 4; tm++) {
                int m = wm * 64 + tm * 16 + (lj & 1) * 8 + lr;
                int k = kk + (lj >> 1) * 8;
                ldm_x4(ah[tm], ah_b + m * 80 + k * 2);
                ldm_x4(al[tm], al_b + m * 80 + k * 2);
            }
            uint32_t bh[2][4], bl[2][4];
#pragma unroll
            for (int tn = 0; tn < 2; tn++) {
                int n = wn * 32 + tn * 16 + (lj >> 1) * 8 + lr;
                int k = kk + (lj & 1) * 8;
                ldm_x4(bh[tn], bh_b + n * 80 + k * 2);
                ldm_x4(bl[tn], bl_b + n * 80 + k * 2);
            }
#pragma unroll
            for (int tm = 0; tm < 4; tm++)
#pragma unroll
                for (int t8 = 0; t8 < 4; t8++) {
                    uint32_t bhr[2] = {bh[t8 >> 1][2 * (t8 & 1)], bh[t8 >> 1][2 * (t8 & 1) + 1]};
                    uint32_t blr[2] = {bl[t8 >> 1][2 * (t8 & 1)], bl[t8 >> 1][2 * (t8 & 1) + 1]};
                    mma_f16(acc[tm][t8], ah[tm], bhr);
                    mma_f16(acc[tm][t8], ah[tm], blr);
                    mma_f16(acc[tm][t8], al[tm], bhr);
                }
        }
        __syncthreads();
    }

    // epilogue: convert fp32 acc -> fp16 hi/lo
#pragma unroll
    for (int tm = 0; tm < 4; tm++) {
        int m = m0 + wm * 64 + tm * 16 + (lane >> 2);
#pragma unroll
        for (int t8 = 0; t8 < 4; t8++) {
            int n = n0 + wn * 32 + t8 * 8 + 2 * (lane & 3);
            float v0 = acc[tm][t8][0], v1 = acc[tm][t8][1];
            float v2 = acc[tm][t8][2], v3 = acc[tm][t8][3];
            __half2 h01 = __floats2half2_rn(v0, v1);
            __half2 h23 = __floats2half2_rn(v2, v3);
            __half2 l01 = __floats2half2_rn(v0 - __low2float(h01), v1 - __high2float(h01));
            __half2 l23 = __floats2half2_rn(v2 - __low2float(h23), v3 - __high2float(h23));
            *(__half2*)(Chi + (size_t)m * N + n) = h01;
            *(__half2*)(Clo + (size_t)m * N + n) = l01;
            *(__half2*)(Chi + (size_t)(m + 8) * N + n) = h23;
            *(__half2*)(Clo + (size_t)(m + 8) * N + n) = l23;
        }
    }
}

// ---------------------------------------------------------------------------
// Tensor-core flash attention. de=128 = [tok(64);pos(64)], fp16 hi/lo split.
// Block: 128 q rows x one (b,h). 8 warps, each owns m16 q rows.
// score = (q.k)*sqrt(128) + bias_table[k-q+1024, h]; online softmax.
// ---------------------------------------------------------------------------
#define QROW 272              // 128 halves + 8 pad, bytes
#define KROW 272
#define VROW 144              // 64 halves + 8 pad
#define KBYTES (64 * KROW)    // 17408
#define VBYTES (64 * VROW)    // 9216
#define STG (2 * KBYTES + 2 * VBYTES + 768)   // K hi/lo, V hi/lo, bias = 54016
#define FL_SMEM (2 * 128 * QROW + 2 * STG)    // 177664

__device__ __forceinline__ void fl_prefetch_tile(uint32_t sb, const float* bias_table,
                                                 int b, int h, int hc, int q0, int k0,
                                                 int s, int tid) {
    const uint32_t kb = sb + 2 * 128 * QROW + s * STG;
    const size_t rb = ((size_t)b * S_LEN + k0) * 3072;
#pragma unroll
    for (int it = 0; it < 4; it++) {
        int e = tid + (it << 8);          // 0..1023
        int k = e >> 4, c = e & 15;
        uint32_t dst = kb + k * KROW + c * 16;
        if (c < 8) {
            size_t so = rb + (size_t)k * 3072 + hc + c * 8;
            cp_async16(dst, g_th + so);
            cp_async16(dst + KBYTES, g_tl + so);
        } else {
            size_t so = (size_t)(k0 + k) * 2048 + hc + (c - 8) * 8;
            cp_async16(dst, g_ph + so);
            cp_async16(dst + KBYTES, g_pl + so);
        }
    }
#pragma unroll
    for (int it = 0; it < 2; it++) {
        int e = tid + (it << 8);          // 0..511
        int k = e >> 3, c = e & 7;
        uint32_t dst = kb + 2 * KBYTES + k * VROW + c * 16;
        size_t so = rb + (size_t)k * 3072 + 2048 + hc + c * 8;
        cp_async16(dst, g_th + so);
        cp_async16(dst + VBYTES, g_tl + so);
    }
    if (tid < 192) {
        int rel = k0 - q0 + 897 + tid;
        rel = rel < 0 ? 0 : (rel > 2047 ? 2047 : rel);
        cp_async4(kb + 2 * KBYTES + 2 * VBYTES + tid * 4, bias_table + rel * N_H + h);
    }
}

__global__ void __launch_bounds__(256, 1) flash_kernel(const float* __restrict__ bias_table,
                                                       float* __restrict__ out) {
    extern __shared__ char sm[];
    const uint32_t sb = smem_u32(sm);
    const int tid = threadIdx.x, lane = tid & 31, wid = tid >> 5;
    const int lj = lane >> 3, lr = lane & 7;
    const int b = blockIdx.z, h = blockIdx.y, q0 = blockIdx.x * 128;
    const int hc = h * 64;
    const int m0w = wid * 16;

    // --- initial: Q tile (hi/lo) + k-tile 0, one commit group ---
    {
        const size_t rb = ((size_t)b * S_LEN + q0) * 3072;
#pragma unroll
        for (int it = 0; it < 8; it++) {
            int e = tid + (it << 8);          // 0..2047
            int q = e >> 4, c = e & 15;
            uint32_t dst = sb + q * QROW + c * 16;
            if (c < 8) {
                size_t so = rb + (size_t)q * 3072 + 1024 + hc + c * 8;
                cp_async16(dst, g_th + so);
                cp_async16(dst + 128 * QROW, g_tl + so);
            } else {
                size_t so = (size_t)(q0 + q) * 2048 + 1024 + hc + (c - 8) * 8;
                cp_async16(dst, g_ph + so);
                cp_async16(dst + 128 * QROW, g_pl + so);
            }
        }
        fl_prefetch_tile(sb, bias_table, b, h, hc, q0, 0, 0, tid);
        CP_COMMIT();
    }

    float O[8][4];
#pragma unroll
    for (int i = 0; i < 8; i++)
#pragma unroll
        for (int j = 0; j < 4; j++) O[i][j] = 0.f;
    float m0 = -INFINITY, m1 = -INFINITY, l0 = 0.f, l1 = 0.f;

    const float SCALE = 11.313708498984761f;   // sqrt(2*dh)
    const float LOG2E = 1.4426950408889634f;
    const int NT = S_LEN / 64;

    for (int kt = 0; kt < NT; kt++) {
        const int s = kt & 1;
        if (kt + 1 < NT) {
            fl_prefetch_tile(sb, bias_table, b, h, hc, q0, (kt + 1) * 64, s ^ 1, tid);
            CP_COMMIT();
            CP_WAIT(1);
        } else {
            CP_WAIT(0);
        }
        __syncthreads();

        const uint32_t khb = sb + 2 * 128 * QROW + s * STG;
        const uint32_t vhb = khb + 2 * KBYTES;
        const float* bias_s = (const float*)(sm + 2 * 128 * QROW + s * STG + 2 * KBYTES + 2 * VBYTES);

        // ---- S = Q K^T (hi/lo 3-pass) ----
        float Sa[8][4];
#pragma unroll
        for (int i = 0; i < 8; i++)
#pragma unroll
            for (int j = 0; j < 4; j++) Sa[i][j] = 0.f;

#pragma unroll
        for (int dk = 0; dk < 8; dk++) {
            uint32_t ah[4], al[4];
            uint32_t qa = sb + (m0w + (lj & 1) * 8 + lr) * QROW + (dk * 16 + (lj >> 1) * 8) * 2;
            ldm_x4(ah, qa);
            ldm_x4(al, qa + 128 * QROW);
#pragma unroll
            for (int ng = 0; ng < 4; ng++) {
                uint32_t bh[4], bl[4];
                uint32_t ka = khb + (ng * 16 + (lj >> 1) * 8 + lr) * KROW + (dk * 16 + (lj & 1) * 8) * 2;
                ldm_x4(bh, ka);
                ldm_x4(bl, ka + KBYTES);
                uint32_t b0[2] = {bh[0], bh[1]}, c0[2] = {bl[0], bl[1]};
                mma_f16(Sa[2 * ng], ah, b0);
                mma_f16(Sa[2 * ng], ah, c0);
                mma_f16(Sa[2 * ng], al, b0);
                uint32_t b1[2] = {bh[2], bh[3]}, c1[2] = {bl[2], bl[3]};
                mma_f16(Sa[2 * ng + 1], ah, b1);
                mma_f16(Sa[2 * ng + 1], ah, c1);
                mma_f16(Sa[2 * ng + 1], al, b1);
            }
        }

        // ---- scale + bias, online softmax, pack P hi/lo ----
        const int ql0 = m0w + (lane >> 2);
        float mx0 = -INFINITY, mx1 = -INFINITY;
#pragma unroll
        for (int tt = 0; tt < 8; tt++) {
            int ib = 127 + 8 * tt + 2 * (lane & 3) - ql0;
            float s0 = Sa[tt][0] * SCALE + bias_s[ib];
            float s1 = Sa[tt][1] * SCALE + bias_s[ib + 1];
            float s2 = Sa[tt][2] * SCALE + bias_s[ib - 8];
            float s3 = Sa[tt][3] * SCALE + bias_s[ib - 7];
            Sa[tt][0] = s0; Sa[tt][1] = s1; Sa[tt][2] = s2; Sa[tt][3] = s3;
            mx0 = fmaxf(mx0, fmaxf(s0, s1));
            mx1 = fmaxf(mx1, fmaxf(s2, s3));
        }
        mx0 = fmaxf(mx0, __shfl_xor_sync(0xffffffffu, mx0, 1));
        mx0 = fmaxf(mx0, __shfl_xor_sync(0xffffffffu, mx0, 2));
        mx1 = fmaxf(mx1, __shfl_xor_sync(0xffffffffu, mx1, 1));
        mx1 = fmaxf(mx1, __shfl_xor_sync(0xffffffffu, mx1, 2));
        float mn0 = fmaxf(m0, mx0), mn1 = fmaxf(m1, mx1);
        float a0 = exp2f((m0 - mn0) * LOG2E), a1 = exp2f((m1 - mn1) * LOG2E);
        m0 = mn0; m1 = mn1;

        uint32_t ph0[8], ph1[8], pl0[8], pl1[8];
        float r0 = 0.f, r1 = 0.f;
#pragma unroll
        for (int tt = 0; tt < 8; tt++) {
            float p0 = exp2f((Sa[tt][0] - m0) * LOG2E);
            float p1 = exp2f((Sa[tt][1] - m0) * LOG2E);
            float p2 = exp2f((Sa[tt][2] - m1) * LOG2E);
            float p3 = exp2f((Sa[tt][3] - m1) * LOG2E);
            r0 += p0 + p1; r1 += p2 + p3;
            __half2 h01 = __floats2half2_rn(p0, p1);
            __half2 h23 = __floats2half2_rn(p2, p3);
            ph0[tt] = h2u(h01);
            ph1[tt] = h2u(h23);
            pl0[tt] = h2u(__floats2half2_rn(p0 - __low2float(h01), p1 - __high2float(h01)));
            pl1[tt] = h2u(__floats2half2_rn(p2 - __low2float(h23), p3 - __high2float(h23)));
        }
        r0 += __shfl_xor_sync(0xffffffffu, r0, 1);
        r0 += __shfl_xor_sync(0xffffffffu, r0, 2);
        r1 += __shfl_xor_sync(0xffffffffu, r1, 1);
        r1 += __shfl_xor_sync(0xffffffffu, r1, 2);
        l0 = l0 * a0 + r0;
        l1 = l1 * a1 + r1;
#pragma unroll
        for (int dt = 0; dt < 8; dt++) {
            O[dt][0] *= a0; O[dt][1] *= a0; O[dt][2] *= a1; O[dt][3] *= a1;
        }

        // ---- O += P V (hi/lo 3-pass), V via ldmatrix.trans ----
#pragma unroll
        for (int ck = 0; ck < 4; ck++) {
            uint32_t Ah[4] = {ph0[2 * ck], ph1[2 * ck], ph0[2 * ck + 1], ph1[2 * ck + 1]};
            uint32_t Al[4] = {pl0[2 * ck], pl1[2 * ck], pl0[2 * ck + 1], pl1[2 * ck + 1]};
#pragma unroll
            for (int dg = 0; dg < 4; dg++) {
                uint32_t vh[4], vl[4];
                uint32_t va = vhb + (ck * 16 + (lj & 1) * 8 + lr) * VROW + (dg * 16 + (lj >> 1) * 8) * 2;
                ldm_x4t(vh, va);
                ldm_x4t(vl, va + VBYTES);
                uint32_t v0[2] = {vh[0], vh[1]}, w0[2] = {vl[0], vl[1]};
                mma_f16(O[2 * dg], Ah, v0);
                mma_f16(O[2 * dg], Ah, w0);
                mma_f16(O[2 * dg], Al, v0);
                uint32_t v1[2] = {vh[2], vh[3]}, w1[2] = {vl[2], vl[3]};
                mma_f16(O[2 * dg + 1], Ah, v1);
                mma_f16(O[2 * dg + 1], Ah, w1);
                mma_f16(O[2 * dg + 1], Al, v1);
            }
        }
        __syncthreads();
    }

    // ---- epilogue ----
    float inv0 = 1.f / l0, inv1 = 1.f / l1;
    size_t row = (size_t)b * S_LEN + q0 + m0w + (lane >> 2);
#pragma unroll
    for (int dt = 0; dt < 8; dt++) {
        int n = hc + dt * 8 + 2 * (lane & 3);
        *(float2*)(out + row * D_MOD + n) = make_float2(O[dt][0] * inv0, O[dt][1] * inv0);
        *(float2*)(out + (row + 8) * D_MOD + n) = make_float2(O[dt][2] * inv1, O[dt][3] * inv1);
    }
}

// ---------------------------------------------------------------------------
// Launch
// ---------------------------------------------------------------------------
extern "C" void kernel_launch(void* const* d_in, const int* in_sizes, int n_in,
                              void* d_out, int out_size) {
    const float* x          = (const float*)d_in[0];
    const float* gamma      = (const float*)d_in[1];
    const float* beta       = (const float*)d_in[2];
    const float* w_pos      = (const float*)d_in[3];
    const float* w_tok      = (const float*)d_in[4];
    const float* bias_table = (const float*)d_in[5];
    float* out = (float*)d_out;

    __half *pe_hi, *pe_lo, *wpos_hi, *wpos_lo, *xn_hi, *xn_lo, *wtok_hi, *wtok_lo;
    __half *ph, *pl, *th, *tl;
    cudaGetSymbolAddress((void**)&pe_hi, g_pe_hi);
    cudaGetSymbolAddress((void**)&pe_lo, g_pe_lo);
    cudaGetSymbolAddress((void**)&wpos_hi, g_wpos_hi);
    cudaGetSymbolAddress((void**)&wpos_lo, g_wpos_lo);
    cudaGetSymbolAddress((void**)&xn_hi, g_xn_hi);
    cudaGetSymbolAddress((void**)&xn_lo, g_xn_lo);
    cudaGetSymbolAddress((void**)&wtok_hi, g_wtok_hi);
    cudaGetSymbolAddress((void**)&wtok_lo, g_wtok_lo);
    cudaGetSymbolAddress((void**)&ph, g_ph);
    cudaGetSymbolAddress((void**)&pl, g_pl);
    cudaGetSymbolAddress((void**)&th, g_th);
    cudaGetSymbolAddress((void**)&tl, g_tl);

    cudaFuncSetAttribute(gemm_f16x2, cudaFuncAttributeMaxDynamicSharedMemorySize, GEMM_SMEM);
    cudaFuncSetAttribute(flash_kernel, cudaFuncAttributeMaxDynamicSharedMemorySize, FL_SMEM);

    pe_kernel<<<S_LEN, 256>>>();
    split_kernel<<<(2 * D_MOD * D_MOD + 255) / 256, 256>>>(w_pos, wpos_hi, wpos_lo, 2 * D_MOD * D_MOD);
    split_kernel<<<(3 * D_MOD * D_MOD + 255) / 256, 256>>>(w_tok, wtok_hi, wtok_lo, 3 * D_MOD * D_MOD);
    ln_kernel<<<B_SZ * S_LEN, 256>>>(x, gamma, beta);
    // pos = pe @ w_pos.T
    gemm_f16x2<<<dim3(2 * D_MOD / 128, S_LEN / 128), 256, GEMM_SMEM>>>(
        pe_hi, pe_lo, wpos_hi, wpos_lo, ph, pl, S_LEN, 2 * D_MOD, D_MOD);
    // tok = xn @ w_tok.T
    gemm_f16x2<<<dim3(3 * D_MOD / 128, B_SZ * S_LEN / 128), 256, GEMM_SMEM>>>(
        xn_hi, xn_lo, wtok_hi, wtok_lo, th, tl, B_SZ * S_LEN, 3 * D_MOD, D_MOD);
    // flash attention (tensor cores)
    flash_kernel<<<dim3(S_LEN / 128, N_H, B_SZ), 256, FL_SMEM>>>(bias_table, out);
}

// round 5
// speedup vs baseline: 3.6730x; 1.1303x over previous
#include <cuda_runtime.h>
#include <cuda_fp16.h>
#include <math.h>
#include <stdint.h>

#define S_LEN 1024
#define D_MOD 1024
#define B_SZ 4
#define N_H 16
#define MAXLEN 1024

// ---------------------------------------------------------------------------
// Scratch (device globals — no allocations allowed)
// ---------------------------------------------------------------------------
__device__ __half g_pe_hi[S_LEN * D_MOD],        g_pe_lo[S_LEN * D_MOD];
__device__ __half g_wpos_hi[2 * D_MOD * D_MOD],  g_wpos_lo[2 * D_MOD * D_MOD];
__device__ __half g_xn_hi[B_SZ * S_LEN * D_MOD], g_xn_lo[B_SZ * S_LEN * D_MOD];
__device__ __half g_wtok_hi[3 * D_MOD * D_MOD],  g_wtok_lo[3 * D_MOD * D_MOD];
__device__ __half g_ph[S_LEN * 2 * D_MOD], g_pl[S_LEN * 2 * D_MOD];                      // pos
__device__ __half g_th[(size_t)B_SZ * S_LEN * 3 * D_MOD], g_tl[(size_t)B_SZ * S_LEN * 3 * D_MOD]; // tok

// ---------------------------------------------------------------------------
// helpers
// ---------------------------------------------------------------------------
__device__ __forceinline__ uint32_t smem_u32(const void* p) {
    uint32_t a;
    asm("{ .reg .u64 t; cvta.to.shared.u64 t, %1; cvt.u32.u64 %0, t; }" : "=r"(a) : "l"(p));
    return a;
}
__device__ __forceinline__ void cp_async16(uint32_t dst, const void* src) {
    asm volatile("cp.async.cg.shared.global [%0], [%1], 16;" :: "r"(dst), "l"(src) : "memory");
}
__device__ __forceinline__ void cp_async4(uint32_t dst, const void* src) {
    asm volatile("cp.async.ca.shared.global [%0], [%1], 4;" :: "r"(dst), "l"(src) : "memory");
}
#define CP_COMMIT() asm volatile("cp.async.commit_group;" ::: "memory")
#define CP_WAIT(n)  asm volatile("cp.async.wait_group %0;" :: "n"(n) : "memory")

__device__ __forceinline__ void ldm_x4(uint32_t* r, uint32_t addr) {
    asm volatile("ldmatrix.sync.aligned.m8n8.x4.shared.b16 {%0,%1,%2,%3}, [%4];"
                 : "=r"(r[0]), "=r"(r[1]), "=r"(r[2]), "=r"(r[3]) : "r"(addr));
}
__device__ __forceinline__ void ldm_x4t(uint32_t* r, uint32_t addr) {
    asm volatile("ldmatrix.sync.aligned.m8n8.x4.trans.shared.b16 {%0,%1,%2,%3}, [%4];"
                 : "=r"(r[0]), "=r"(r[1]), "=r"(r[2]), "=r"(r[3]) : "r"(addr));
}
__device__ __forceinline__ void mma_f16(float* c, const uint32_t* a, const uint32_t* b) {
    asm volatile("mma.sync.aligned.m16n8k16.row.col.f32.f16.f16.f32 "
                 "{%0,%1,%2,%3}, {%4,%5,%6,%7}, {%8,%9}, {%0,%1,%2,%3};"
                 : "+f"(c[0]), "+f"(c[1]), "+f"(c[2]), "+f"(c[3])
                 : "r"(a[0]), "r"(a[1]), "r"(a[2]), "r"(a[3]), "r"(b[0]), "r"(b[1]));
}
__device__ __forceinline__ uint32_t h2u(__half2 h) { return *reinterpret_cast<uint32_t*>(&h); }

// ---------------------------------------------------------------------------
// PE (sinusoidal) -> fp16 hi/lo split
// ---------------------------------------------------------------------------
__global__ void pe_kernel() {
    int s = blockIdx.x;
    for (int d = threadIdx.x; d < D_MOD; d += blockDim.x) {
        int i = d >> 1;
        float div = expf((float)(2 * i) * (-9.210340371976184f / (float)D_MOD));
        float ang = (float)s * div;
        float v = (d & 1) ? cosf(ang) : sinf(ang);
        __half h = __float2half_rn(v);
        g_pe_hi[s * D_MOD + d] = h;
        g_pe_lo[s * D_MOD + d] = __float2half_rn(v - __half2float(h));
    }
}

__global__ void split_kernel(const float* __restrict__ src, __half* __restrict__ hi,
                             __half* __restrict__ lo, int n) {
    int i = blockIdx.x * blockDim.x + threadIdx.x;
    if (i < n) {
        float x = src[i];
        __half h = __float2half_rn(x);
        hi[i] = h;
        lo[i] = __float2half_rn(x - __half2float(h));
    }
}

// ---------------------------------------------------------------------------
// LayerNorm -> fp16 hi/lo split
// ---------------------------------------------------------------------------
__global__ void __launch_bounds__(256) ln_kernel(const float* __restrict__ x,
                                                 const float* __restrict__ gamma,
                                                 const float* __restrict__ beta) {
    const int row = blockIdx.x;
    const float* xr = x + (size_t)row * D_MOD;
    const int t = threadIdx.x;
    const int lane = t & 31, wid = t >> 5;
    __shared__ float red[8];

    float v[4];
    float s = 0.f;
#pragma unroll
    for (int i = 0; i < 4; i++) { v[i] = xr[t + i * 256]; s += v[i]; }
#pragma unroll
    for (int o = 16; o > 0; o >>= 1) s += __shfl_xor_sync(0xffffffffu, s, o);
    if (lane == 0) red[wid] = s;
    __syncthreads();
    float tot = 0.f;
#pragma unroll
    for (int i = 0; i < 8; i++) tot += red[i];
    float mean = tot * (1.f / 1024.f);

    float sq = 0.f;
#pragma unroll
    for (int i = 0; i < 4; i++) { float d = v[i] - mean; sq += d * d; }
#pragma unroll
    for (int o = 16; o > 0; o >>= 1) sq += __shfl_xor_sync(0xffffffffu, sq, o);
    __syncthreads();
    if (lane == 0) red[wid] = sq;
    __syncthreads();
    float tot2 = 0.f;
#pragma unroll
    for (int i = 0; i < 8; i++) tot2 += red[i];
    float rstd = rsqrtf(tot2 * (1.f / 1024.f) + 1e-5f);

#pragma unroll
    for (int i = 0; i < 4; i++) {
        int c = t + i * 256;
        float y = (v[i] - mean) * rstd * gamma[c] + beta[c];
        __half h = __float2half_rn(y);
        g_xn_hi[(size_t)row * D_MOD + c] = h;
        g_xn_lo[(size_t)row * D_MOD + c] = __float2half_rn(y - __half2float(h));
    }
}

// ---------------------------------------------------------------------------
// mma.sync fp16x2-split NT GEMM: C = A[M,K] * B[N,K]^T, fp16 hi/lo output
// Blocks with n0 >= n2pass use 2-pass (drop Al pass) — for V columns.
// ---------------------------------------------------------------------------
#define OPBUF 10240
#define GEMM_SMEM (8 * OPBUF)

__global__ void __launch_bounds__(256) gemm_f16x2(
    const __half* __restrict__ Ahi, const __half* __restrict__ Alo,
    const __half* __restrict__ Bhi, const __half* __restrict__ Blo,
    __half* __restrict__ Chi, __half* __restrict__ Clo, int M, int N, int K, int n2pass)
{
    extern __shared__ char sm[];
    const uint32_t sb = smem_u32(sm);
    const int tid = threadIdx.x;
    const int lane = tid & 31, wid = tid >> 5;
    const int wm = wid >> 2, wn = wid & 3;
    const int m0 = blockIdx.y * 128, n0 = blockIdx.x * 128;
    const bool full = (n0 < n2pass);

    float acc[4][4][4];
#pragma unroll
    for (int i = 0; i < 4; i++)
#pragma unroll
        for (int j = 0; j < 4; j++)
#pragma unroll
            for (int r = 0; r < 4; r++) acc[i][j][r] = 0.f;

    const __half* srcs[4] = {Ahi, Alo, Bhi, Blo};
    const int rows0[4] = {m0, m0, n0, n0};
    const int NCH = K >> 5;
    const int lj = lane >> 3, lr = lane & 7;

#pragma unroll
    for (int op = 0; op < 4; op++) {
        if (op == 1 && !full) continue;
#pragma unroll
        for (int it = 0; it < 2; it++) {
            int e = tid + (it << 8);
            int r = e >> 2, cs = e & 3;
            cp_async16(sb + op * OPBUF + r * 80 + cs * 16,
                       srcs[op] + (size_t)(rows0[op] + r) * K + (cs << 3));
        }
    }
    CP_COMMIT();

    for (int i = 0; i < NCH; i++) {
        const int s = i & 1;
        if (i + 1 < NCH) {
            const int s2 = s ^ 1, k0 = (i + 1) << 5;
#pragma unroll
            for (int op = 0; op < 4; op++) {
                if (op == 1 && !full) continue;
#pragma unroll
                for (int it = 0; it < 2; it++) {
                    int e = tid + (it << 8);
                    int r = e >> 2, cs = e & 3;
                    cp_async16(sb + (s2 * 4 + op) * OPBUF + r * 80 + cs * 16,
                               srcs[op] + (size_t)(rows0[op] + r) * K + k0 + (cs << 3));
                }
            }
            CP_COMMIT();
            CP_WAIT(1);
        } else {
            CP_WAIT(0);
        }
        __syncthreads();

        const uint32_t ah_b = sb + (s * 4 + 0) * OPBUF;
        const uint32_t al_b = sb + (s * 4 + 1) * OPBUF;
        const uint32_t bh_b = sb + (s * 4 + 2) * OPBUF;
        const uint32_t bl_b = sb + (s * 4 + 3) * OPBUF;

#pragma unroll
        for (int kk = 0; kk < 32; kk += 16) {
            uint32_t ah[4][4], al[4][4];
#pragma unroll
            for (int tm = 0; tm < 4; tm++) {
                int m = wm * 64 + tm * 16 + (lj & 1) * 8 + lr;
                int k = kk + (lj >> 1) * 8;
                ldm_x4(ah[tm], ah_b + m * 80 + k * 2);
                if (full) ldm_x4(al[tm], al_b + m * 80 + k * 2);
            }
            uint32_t bh[2][4], bl[2][4];
#pragma unroll
            for (int tn = 0; tn < 2; tn++) {
                int n = wn * 32 + tn * 16 + (lj >> 1) * 8 + lr;
                int k = kk + (lj & 1) * 8;
                ldm_x4(bh[tn], bh_b + n * 80 + k * 2);
                ldm_x4(bl[tn], bl_b + n * 80 + k * 2);
            }
#pragma unroll
            for (int tm = 0; tm < 4; tm++)
#pragma unroll
                for (int t8 = 0; t8 < 4; t8++) {
                    uint32_t bhr[2] = {bh[t8 >> 1][2 * (t8 & 1)], bh[t8 >> 1][2 * (t8 & 1) + 1]};
                    uint32_t blr[2] = {bl[t8 >> 1][2 * (t8 & 1)], bl[t8 >> 1][2 * (t8 & 1) + 1]};
                    mma_f16(acc[tm][t8], ah[tm], bhr);
                    mma_f16(acc[tm][t8], ah[tm], blr);
                    if (full) mma_f16(acc[tm][t8], al[tm], bhr);
                }
        }
        __syncthreads();
    }

#pragma unroll
    for (int tm = 0; tm < 4; tm++) {
        int m = m0 + wm * 64 + tm * 16 + (lane >> 2);
#pragma unroll
        for (int t8 = 0; t8 < 4; t8++) {
            int n = n0 + wn * 32 + t8 * 8 + 2 * (lane & 3);
            float v0 = acc[tm][t8][0], v1 = acc[tm][t8][1];
            float v2 = acc[tm][t8][2], v3 = acc[tm][t8][3];
            __half2 h01 = __floats2half2_rn(v0, v1);
            __half2 h23 = __floats2half2_rn(v2, v3);
            *(__half2*)(Chi + (size_t)m * N + n) = h01;
            *(__half2*)(Chi + (size_t)(m + 8) * N + n) = h23;
            if (full) {
                __half2 l01 = __floats2half2_rn(v0 - __low2float(h01), v1 - __high2float(h01));
                __half2 l23 = __floats2half2_rn(v2 - __low2float(h23), v3 - __high2float(h23));
                *(__half2*)(Clo + (size_t)m * N + n) = l01;
                *(__half2*)(Clo + (size_t)(m + 8) * N + n) = l23;
            }
        }
    }
}

// ---------------------------------------------------------------------------
// Tensor-core flash attention. de=128 = [tok(64);pos(64)], QK fp16 hi/lo 3-pass,
// PV single-pass (P-hi x V-hi). Block: 128 q rows x one (b,h); 8 warps.
// ---------------------------------------------------------------------------
#define QROW 272              // 128 halves + 8 pad, bytes
#define KROW 272
#define VROW 144              // 64 halves + 8 pad
#define KBYTES (64 * KROW)    // 17408
#define VBYTES (64 * VROW)    // 9216
#define STG (2 * KBYTES + VBYTES + 768)       // K hi/lo, V hi, bias = 44800
#define FL_SMEM (2 * 128 * QROW + 2 * STG)    // 159232

__device__ __forceinline__ void fl_prefetch_tile(uint32_t sb, const float* bias_table,
                                                 int b, int h, int hc, int q0, int k0,
                                                 int s, int tid) {
    const uint32_t kb = sb + 2 * 128 * QROW + s * STG;
    const size_t rb = ((size_t)b * S_LEN + k0) * 3072;
#pragma unroll
    for (int it = 0; it < 4; it++) {
        int e = tid + (it << 8);          // 0..1023
        int k = e >> 4, c = e & 15;
        uint32_t dst = kb + k * KROW + c * 16;
        if (c < 8) {
            size_t so = rb + (size_t)k * 3072 + hc + c * 8;
            cp_async16(dst, g_th + so);
            cp_async16(dst + KBYTES, g_tl + so);
        } else {
            size_t so = (size_t)(k0 + k) * 2048 + hc + (c - 8) * 8;
            cp_async16(dst, g_ph + so);
            cp_async16(dst + KBYTES, g_pl + so);
        }
    }
#pragma unroll
    for (int it = 0; it < 2; it++) {
        int e = tid + (it << 8);          // 0..511
        int k = e >> 3, c = e & 7;
        size_t so = rb + (size_t)k * 3072 + 2048 + hc + c * 8;
        cp_async16(kb + 2 * KBYTES + k * VROW + c * 16, g_th + so);
    }
    if (tid < 192) {
        int rel = k0 - q0 + 897 + tid;
        rel = rel < 0 ? 0 : (rel > 2047 ? 2047 : rel);
        cp_async4(kb + 2 * KBYTES + VBYTES + tid * 4, bias_table + rel * N_H + h);
    }
}

__global__ void __launch_bounds__(256, 1) flash_kernel(const float* __restrict__ bias_table,
                                                       float* __restrict__ out) {
    extern __shared__ char sm[];
    const uint32_t sb = smem_u32(sm);
    const int tid = threadIdx.x, lane = tid & 31, wid = tid >> 5;
    const int lj = lane >> 3, lr = lane & 7;
    const int b = blockIdx.z, h = blockIdx.y, q0 = blockIdx.x * 128;
    const int hc = h * 64;
    const int m0w = wid * 16;

    {
        const size_t rb = ((size_t)b * S_LEN + q0) * 3072;
#pragma unroll
        for (int it = 0; it < 8; it++) {
            int e = tid + (it << 8);          // 0..2047
            int q = e >> 4, c = e & 15;
            uint32_t dst = sb + q * QROW + c * 16;
            if (c < 8) {
                size_t so = rb + (size_t)q * 3072 + 1024 + hc + c * 8;
                cp_async16(dst, g_th + so);
                cp_async16(dst + 128 * QROW, g_tl + so);
            } else {
                size_t so = (size_t)(q0 + q) * 2048 + 1024 + hc + (c - 8) * 8;
                cp_async16(dst, g_ph + so);
                cp_async16(dst + 128 * QROW, g_pl + so);
            }
        }
        fl_prefetch_tile(sb, bias_table, b, h, hc, q0, 0, 0, tid);
        CP_COMMIT();
    }

    float O[8][4];
#pragma unroll
    for (int i = 0; i < 8; i++)
#pragma unroll
        for (int j = 0; j < 4; j++) O[i][j] = 0.f;
    float m0 = -INFINITY, m1 = -INFINITY, l0 = 0.f, l1 = 0.f;

    const float SCALE = 11.313708498984761f;
    const float LOG2E = 1.4426950408889634f;
    const int NT = S_LEN / 64;

    for (int kt = 0; kt < NT; kt++) {
        const int s = kt & 1;
        if (kt + 1 < NT) {
            fl_prefetch_tile(sb, bias_table, b, h, hc, q0, (kt + 1) * 64, s ^ 1, tid);
            CP_COMMIT();
            CP_WAIT(1);
        } else {
            CP_WAIT(0);
        }
        __syncthreads();

        const uint32_t khb = sb + 2 * 128 * QROW + s * STG;
        const uint32_t vhb = khb + 2 * KBYTES;
        const float* bias_s = (const float*)(sm + 2 * 128 * QROW + s * STG + 2 * KBYTES + VBYTES);

        // ---- S = Q K^T (hi/lo 3-pass) ----
        float Sa[8][4];
#pragma unroll
        for (int i = 0; i < 8; i++)
#pragma unroll
            for (int j = 0; j < 4; j++) Sa[i][j] = 0.f;

#pragma unroll
        for (int dk = 0; dk < 8; dk++) {
            uint32_t ah[4], al[4];
            uint32_t qa = sb + (m0w + (lj & 1) * 8 + lr) * QROW + (dk * 16 + (lj >> 1) * 8) * 2;
            ldm_x4(ah, qa);
            ldm_x4(al, qa + 128 * QROW);
#pragma unroll
            for (int ng = 0; ng < 4; ng++) {
                uint32_t bh[4], bl[4];
                uint32_t ka = khb + (ng * 16 + (lj >> 1) * 8 + lr) * KROW + (dk * 16 + (lj & 1) * 8) * 2;
                ldm_x4(bh, ka);
                ldm_x4(bl, ka + KBYTES);
                uint32_t b0[2] = {bh[0], bh[1]}, c0[2] = {bl[0], bl[1]};
                mma_f16(Sa[2 * ng], ah, b0);
                mma_f16(Sa[2 * ng], ah, c0);
                mma_f16(Sa[2 * ng], al, b0);
                uint32_t b1[2] = {bh[2], bh[3]}, c1[2] = {bl[2], bl[3]};
                mma_f16(Sa[2 * ng + 1], ah, b1);
                mma_f16(Sa[2 * ng + 1], ah, c1);
                mma_f16(Sa[2 * ng + 1], al, b1);
            }
        }

        // ---- scale + bias, online softmax, pack P (hi only) ----
        const int ql0 = m0w + (lane >> 2);
        float mx0 = -INFINITY, mx1 = -INFINITY;
#pragma unroll
        for (int tt = 0; tt < 8; tt++) {
            int ib = 127 + 8 * tt + 2 * (lane & 3) - ql0;
            float s0 = Sa[tt][0] * SCALE + bias_s[ib];
            float s1 = Sa[tt][1] * SCALE + bias_s[ib + 1];
            float s2 = Sa[tt][2] * SCALE + bias_s[ib - 8];
            float s3 = Sa[tt][3] * SCALE + bias_s[ib - 7];
            Sa[tt][0] = s0; Sa[tt][1] = s1; Sa[tt][2] = s2; Sa[tt][3] = s3;
            mx0 = fmaxf(mx0, fmaxf(s0, s1));
            mx1 = fmaxf(mx1, fmaxf(s2, s3));
        }
        mx0 = fmaxf(mx0, __shfl_xor_sync(0xffffffffu, mx0, 1));
        mx0 = fmaxf(mx0, __shfl_xor_sync(0xffffffffu, mx0, 2));
        mx1 = fmaxf(mx1, __shfl_xor_sync(0xffffffffu, mx1, 1));
        mx1 = fmaxf(mx1, __shfl_xor_sync(0xffffffffu, mx1, 2));
        float mn0 = fmaxf(m0, mx0), mn1 = fmaxf(m1, mx1);
        float a0 = exp2f((m0 - mn0) * LOG2E), a1 = exp2f((m1 - mn1) * LOG2E);
        m0 = mn0; m1 = mn1;

        uint32_t ph0[8], ph1[8];
        float r0 = 0.f, r1 = 0.f;
#pragma unroll
        for (int tt = 0; tt < 8; tt++) {
            float p0 = exp2f((Sa[tt][0] - m0) * LOG2E);
            float p1 = exp2f((Sa[tt][1] - m0) * LOG2E);
            float p2 = exp2f((Sa[tt][2] - m1) * LOG2E);
            float p3 = exp2f((Sa[tt][3] - m1) * LOG2E);
            r0 += p0 + p1; r1 += p2 + p3;
            ph0[tt] = h2u(__floats2half2_rn(p0, p1));
            ph1[tt] = h2u(__floats2half2_rn(p2, p3));
        }
        r0 += __shfl_xor_sync(0xffffffffu, r0, 1);
        r0 += __shfl_xor_sync(0xffffffffu, r0, 2);
        r1 += __shfl_xor_sync(0xffffffffu, r1, 1);
        r1 += __shfl_xor_sync(0xffffffffu, r1, 2);
        l0 = l0 * a0 + r0;
        l1 = l1 * a1 + r1;
#pragma unroll
        for (int dt = 0; dt < 8; dt++) {
            O[dt][0] *= a0; O[dt][1] *= a0; O[dt][2] *= a1; O[dt][3] *= a1;
        }

        // ---- O += P V (single pass), V via ldmatrix.trans ----
#pragma unroll
        for (int ck = 0; ck < 4; ck++) {
            uint32_t Ah[4] = {ph0[2 * ck], ph1[2 * ck], ph0[2 * ck + 1], ph1[2 * ck + 1]};
#pragma unroll
            for (int dg = 0; dg < 4; dg++) {
                uint32_t vh[4];
                uint32_t va = vhb + (ck * 16 + (lj & 1) * 8 + lr) * VROW + (dg * 16 + (lj >> 1) * 8) * 2;
                ldm_x4t(vh, va);
                uint32_t v0[2] = {vh[0], vh[1]};
                mma_f16(O[2 * dg], Ah, v0);
                uint32_t v1[2] = {vh[2], vh[3]};
                mma_f16(O[2 * dg + 1], Ah, v1);
            }
        }
        __syncthreads();
    }

    // ---- epilogue ----
    float inv0 = 1.f / l0, inv1 = 1.f / l1;
    size_t row = (size_t)b * S_LEN + q0 + m0w + (lane >> 2);
#pragma unroll
    for (int dt = 0; dt < 8; dt++) {
        int n = hc + dt * 8 + 2 * (lane & 3);
        *(float2*)(out + row * D_MOD + n) = make_float2(O[dt][0] * inv0, O[dt][1] * inv0);
        *(float2*)(out + (row + 8) * D_MOD + n) = make_float2(O[dt][2] * inv1, O[dt][3] * inv1);
    }
}

// ---------------------------------------------------------------------------
// Launch
// ---------------------------------------------------------------------------
extern "C" void kernel_launch(void* const* d_in, const int* in_sizes, int n_in,
                              void* d_out, int out_size) {
    const float* x          = (const float*)d_in[0];
    const float* gamma      = (const float*)d_in[1];
    const float* beta       = (const float*)d_in[2];
    const float* w_pos      = (const float*)d_in[3];
    const float* w_tok      = (const float*)d_in[4];
    const float* bias_table = (const float*)d_in[5];
    float* out = (float*)d_out;

    __half *pe_hi, *pe_lo, *wpos_hi, *wpos_lo, *xn_hi, *xn_lo, *wtok_hi, *wtok_lo;
    __half *ph, *pl, *th, *tl;
    cudaGetSymbolAddress((void**)&pe_hi, g_pe_hi);
    cudaGetSymbolAddress((void**)&pe_lo, g_pe_lo);
    cudaGetSymbolAddress((void**)&wpos_hi, g_wpos_hi);
    cudaGetSymbolAddress((void**)&wpos_lo, g_wpos_lo);
    cudaGetSymbolAddress((void**)&xn_hi, g_xn_hi);
    cudaGetSymbolAddress((void**)&xn_lo, g_xn_lo);
    cudaGetSymbolAddress((void**)&wtok_hi, g_wtok_hi);
    cudaGetSymbolAddress((void**)&wtok_lo, g_wtok_lo);
    cudaGetSymbolAddress((void**)&ph, g_ph);
    cudaGetSymbolAddress((void**)&pl, g_pl);
    cudaGetSymbolAddress((void**)&th, g_th);
    cudaGetSymbolAddress((void**)&tl, g_tl);

    cudaFuncSetAttribute(gemm_f16x2, cudaFuncAttributeMaxDynamicSharedMemorySize, GEMM_SMEM);
    cudaFuncSetAttribute(flash_kernel, cudaFuncAttributeMaxDynamicSharedMemorySize, FL_SMEM);

    pe_kernel<<<S_LEN, 256>>>();
    split_kernel<<<(2 * D_MOD * D_MOD + 255) / 256, 256>>>(w_pos, wpos_hi, wpos_lo, 2 * D_MOD * D_MOD);
    split_kernel<<<(3 * D_MOD * D_MOD + 255) / 256, 256>>>(w_tok, wtok_hi, wtok_lo, 3 * D_MOD * D_MOD);
    ln_kernel<<<B_SZ * S_LEN, 256>>>(x, gamma, beta);
    // pos = pe @ w_pos.T  (full precision everywhere)
    gemm_f16x2<<<dim3(2 * D_MOD / 128, S_LEN / 128), 256, GEMM_SMEM>>>(
        pe_hi, pe_lo, wpos_hi, wpos_lo, ph, pl, S_LEN, 2 * D_MOD, D_MOD, 2 * D_MOD);
    // tok = xn @ w_tok.T  (V columns n>=2048: 2-pass)
    gemm_f16x2<<<dim3(3 * D_MOD / 128, B_SZ * S_LEN / 128), 256, GEMM_SMEM>>>(
        xn_hi, xn_lo, wtok_hi, wtok_lo, th, tl, B_SZ * S_LEN, 3 * D_MOD, D_MOD, 2 * D_MOD);
    // flash attention (tensor cores)
    flash_kernel<<<dim3(S_LEN / 128, N_H, B_SZ), 256, FL_SMEM>>>(bias_table, out);
}

// round 7
// speedup vs baseline: 4.1000x; 1.1163x over previous
#include <cuda_runtime.h>
#include <cuda_fp16.h>
#include <math.h>
#include <stdint.h>

#define S_LEN 1024
#define D_MOD 1024
#define B_SZ 4
#define N_H 16
#define MAXLEN 1024

// ---------------------------------------------------------------------------
// Scratch (device globals — no allocations allowed)
// ---------------------------------------------------------------------------
__device__ __half g_pe_hi[S_LEN * D_MOD],        g_pe_lo[S_LEN * D_MOD];
__device__ __half g_wpos_hi[2 * D_MOD * D_MOD],  g_wpos_lo[2 * D_MOD * D_MOD];
__device__ __half g_xn_hi[B_SZ * S_LEN * D_MOD], g_xn_lo[B_SZ * S_LEN * D_MOD];
__device__ __half g_wtok_hi[3 * D_MOD * D_MOD],  g_wtok_lo[3 * D_MOD * D_MOD];
__device__ __half g_ph[S_LEN * 2 * D_MOD], g_pl[S_LEN * 2 * D_MOD];                      // pos
__device__ __half g_th[(size_t)B_SZ * S_LEN * 3 * D_MOD], g_tl[(size_t)B_SZ * S_LEN * 3 * D_MOD]; // tok

// ---------------------------------------------------------------------------
// helpers
// ---------------------------------------------------------------------------
__device__ __forceinline__ uint32_t smem_u32(const void* p) {
    uint32_t a;
    asm("{ .reg .u64 t; cvta.to.shared.u64 t, %1; cvt.u32.u64 %0, t; }" : "=r"(a) : "l"(p));
    return a;
}
__device__ __forceinline__ void cp_async16(uint32_t dst, const void* src) {
    asm volatile("cp.async.cg.shared.global [%0], [%1], 16;" :: "r"(dst), "l"(src) : "memory");
}
__device__ __forceinline__ void cp_async4(uint32_t dst, const void* src) {
    asm volatile("cp.async.ca.shared.global [%0], [%1], 4;" :: "r"(dst), "l"(src) : "memory");
}
#define CP_COMMIT() asm volatile("cp.async.commit_group;" ::: "memory")
#define CP_WAIT(n)  asm volatile("cp.async.wait_group %0;" :: "n"(n) : "memory")

__device__ __forceinline__ void ldm_x4(uint32_t* r, uint32_t addr) {
    asm volatile("ldmatrix.sync.aligned.m8n8.x4.shared.b16 {%0,%1,%2,%3}, [%4];"
                 : "=r"(r[0]), "=r"(r[1]), "=r"(r[2]), "=r"(r[3]) : "r"(addr));
}
__device__ __forceinline__ void ldm_x4t(uint32_t* r, uint32_t addr) {
    asm volatile("ldmatrix.sync.aligned.m8n8.x4.trans.shared.b16 {%0,%1,%2,%3}, [%4];"
                 : "=r"(r[0]), "=r"(r[1]), "=r"(r[2]), "=r"(r[3]) : "r"(addr));
}
__device__ __forceinline__ void mma_f16(float* c, const uint32_t* a, const uint32_t* b) {
    asm volatile("mma.sync.aligned.m16n8k16.row.col.f32.f16.f16.f32 "
                 "{%0,%1,%2,%3}, {%4,%5,%6,%7}, {%8,%9}, {%0,%1,%2,%3};"
                 : "+f"(c[0]), "+f"(c[1]), "+f"(c[2]), "+f"(c[3])
                 : "r"(a[0]), "r"(a[1]), "r"(a[2]), "r"(a[3]), "r"(b[0]), "r"(b[1]));
}
__device__ __forceinline__ uint32_t h2u(__half2 h) { return *reinterpret_cast<uint32_t*>(&h); }

// ---------------------------------------------------------------------------
// PE (sinusoidal) -> fp16 hi/lo split
// ---------------------------------------------------------------------------
__global__ void pe_kernel() {
    int s = blockIdx.x;
    for (int d = threadIdx.x; d < D_MOD; d += blockDim.x) {
        int i = d >> 1;
        float div = expf((float)(2 * i) * (-9.210340371976184f / (float)D_MOD));
        float ang = (float)s * div;
        float v = (d & 1) ? cosf(ang) : sinf(ang);
        __half h = __float2half_rn(v);
        g_pe_hi[s * D_MOD + d] = h;
        g_pe_lo[s * D_MOD + d] = __float2half_rn(v - __half2float(h));
    }
}

__global__ void split_kernel(const float* __restrict__ src, __half* __restrict__ hi,
                             __half* __restrict__ lo, int n) {
    int i = blockIdx.x * blockDim.x + threadIdx.x;
    if (i < n) {
        float x = src[i];
        __half h = __float2half_rn(x);
        hi[i] = h;
        lo[i] = __float2half_rn(x - __half2float(h));
    }
}

// ---------------------------------------------------------------------------
// LayerNorm -> fp16 hi/lo split
// ---------------------------------------------------------------------------
__global__ void __launch_bounds__(256) ln_kernel(const float* __restrict__ x,
                                                 const float* __restrict__ gamma,
                                                 const float* __restrict__ beta) {
    const int row = blockIdx.x;
    const float* xr = x + (size_t)row * D_MOD;
    const int t = threadIdx.x;
    const int lane = t & 31, wid = t >> 5;
    __shared__ float red[8];

    float v[4];
    float s = 0.f;
#pragma unroll
    for (int i = 0; i < 4; i++) { v[i] = xr[t + i * 256]; s += v[i]; }
#pragma unroll
    for (int o = 16; o > 0; o >>= 1) s += __shfl_xor_sync(0xffffffffu, s, o);
    if (lane == 0) red[wid] = s;
    __syncthreads();
    float tot = 0.f;
#pragma unroll
    for (int i = 0; i < 8; i++) tot += red[i];
    float mean = tot * (1.f / 1024.f);

    float sq = 0.f;
#pragma unroll
    for (int i = 0; i < 4; i++) { float d = v[i] - mean; sq += d * d; }
#pragma unroll
    for (int o = 16; o > 0; o >>= 1) sq += __shfl_xor_sync(0xffffffffu, sq, o);
    __syncthreads();
    if (lane == 0) red[wid] = sq;
    __syncthreads();
    float tot2 = 0.f;
#pragma unroll
    for (int i = 0; i < 8; i++) tot2 += red[i];
    float rstd = rsqrtf(tot2 * (1.f / 1024.f) + 1e-5f);

#pragma unroll
    for (int i = 0; i < 4; i++) {
        int c = t + i * 256;
        float y = (v[i] - mean) * rstd * gamma[c] + beta[c];
        __half h = __float2half_rn(y);
        g_xn_hi[(size_t)row * D_MOD + c] = h;
        g_xn_lo[(size_t)row * D_MOD + c] = __float2half_rn(y - __half2float(h));
    }
}

// ---------------------------------------------------------------------------
// mma.sync fp16x2-split NT GEMM body (device fn), merged launch for pos+tok
// ---------------------------------------------------------------------------
#define OPBUF 10240
#define GEMM_SMEM (8 * OPBUF)

__device__ __forceinline__ void gemm_body(
    const __half* __restrict__ Ahi, const __half* __restrict__ Alo,
    const __half* __restrict__ Bhi, const __half* __restrict__ Blo,
    __half* __restrict__ Chi, __half* __restrict__ Clo,
    int N, int K, int m0, int n0, bool full, char* sm)
{
    const uint32_t sb = smem_u32(sm);
    const int tid = threadIdx.x;
    const int lane = tid & 31, wid = tid >> 5;
    const int wm = wid >> 2, wn = wid & 3;

    float acc[4][4][4];
#pragma unroll
    for (int i = 0; i < 4; i++)
#pragma unroll
        for (int j = 0; j < 4; j++)
#pragma unroll
            for (int r = 0; r < 4; r++) acc[i][j][r] = 0.f;

    const __half* srcs[4] = {Ahi, Alo, Bhi, Blo};
    const int rows0[4] = {m0, m0, n0, n0};
    const int NCH = K >> 5;
    const int lj = lane >> 3, lr = lane & 7;

#pragma unroll
    for (int op = 0; op < 4; op++) {
        if (op == 1 && !full) continue;
#pragma unroll
        for (int it = 0; it < 2; it++) {
            int e = tid + (it << 8);
            int r = e >> 2, cs = e & 3;
            cp_async16(sb + op * OPBUF + r * 80 + cs * 16,
                       srcs[op] + (size_t)(rows0[op] + r) * K + (cs << 3));
        }
    }
    CP_COMMIT();

    for (int i = 0; i < NCH; i++) {
        const int s = i & 1;
        if (i + 1 < NCH) {
            const int s2 = s ^ 1, k0 = (i + 1) << 5;
#pragma unroll
            for (int op = 0; op < 4; op++) {
                if (op == 1 && !full) continue;
#pragma unroll
                for (int it = 0; it < 2; it++) {
                    int e = tid + (it << 8);
                    int r = e >> 2, cs = e & 3;
                    cp_async16(sb + (s2 * 4 + op) * OPBUF + r * 80 + cs * 16,
                               srcs[op] + (size_t)(rows0[op] + r) * K + k0 + (cs << 3));
                }
            }
            CP_COMMIT();
            CP_WAIT(1);
        } else {
            CP_WAIT(0);
        }
        __syncthreads();

        const uint32_t ah_b = sb + (s * 4 + 0) * OPBUF;
        const uint32_t al_b = sb + (s * 4 + 1) * OPBUF;
        const uint32_t bh_b = sb + (s * 4 + 2) * OPBUF;
        const uint32_t bl_b = sb + (s * 4 + 3) * OPBUF;

#pragma unroll
        for (int kk = 0; kk < 32; kk += 16) {
            uint32_t ah[4][4], al[4][4];
#pragma unroll
            for (int tm = 0; tm < 4; tm++) {
                int m = wm * 64 + tm * 16 + (lj & 1) * 8 + lr;
                int k = kk + (lj >> 1) * 8;
                ldm_x4(ah[tm], ah_b + m * 80 + k * 2);
                if (full) ldm_x4(al[tm], al_b + m * 80 + k * 2);
            }
            uint32_t bh[2][4], bl[2][4];
#pragma unroll
            for (int tn = 0; tn < 2; tn++) {
                int n = wn * 32 + tn * 16 + (lj >> 1) * 8 + lr;
                int k = kk + (lj & 1) * 8;
                ldm_x4(bh[tn], bh_b + n * 80 + k * 2);
                ldm_x4(bl[tn], bl_b + n * 80 + k * 2);
            }
#pragma unroll
            for (int tm = 0; tm < 4; tm++)
#pragma unroll
                for (int t8 = 0; t8 < 4; t8++) {
                    uint32_t bhr[2] = {bh[t8 >> 1][2 * (t8 & 1)], bh[t8 >> 1][2 * (t8 & 1) + 1]};
                    uint32_t blr[2] = {bl[t8 >> 1][2 * (t8 & 1)], bl[t8 >> 1][2 * (t8 & 1) + 1]};
                    mma_f16(acc[tm][t8], ah[tm], bhr);
                    mma_f16(acc[tm][t8], ah[tm], blr);
                    if (full) mma_f16(acc[tm][t8], al[tm], bhr);
                }
        }
        __syncthreads();
    }

#pragma unroll
    for (int tm = 0; tm < 4; tm++) {
        int m = m0 + wm * 64 + tm * 16 + (lane >> 2);
#pragma unroll
        for (int t8 = 0; t8 < 4; t8++) {
            int n = n0 + wn * 32 + t8 * 8 + 2 * (lane & 3);
            float v0 = acc[tm][t8][0], v1 = acc[tm][t8][1];
            float v2 = acc[tm][t8][2], v3 = acc[tm][t8][3];
            __half2 h01 = __floats2half2_rn(v0, v1);
            __half2 h23 = __floats2half2_rn(v2, v3);
            *(__half2*)(Chi + (size_t)m * N + n) = h01;
            *(__half2*)(Chi + (size_t)(m + 8) * N + n) = h23;
            if (full) {
                __half2 l01 = __floats2half2_rn(v0 - __low2float(h01), v1 - __high2float(h01));
                __half2 l23 = __floats2half2_rn(v2 - __low2float(h23), v3 - __high2float(h23));
                *(__half2*)(Clo + (size_t)m * N + n) = l01;
                *(__half2*)(Clo + (size_t)(m + 8) * N + n) = l23;
            }
        }
    }
}

// merged launch: blocks [0,768) = tok (24 x 32), blocks [768,896) = pos (16 x 8)
__global__ void __launch_bounds__(256) gemm_merged() {
    extern __shared__ char sm[];
    int bx = blockIdx.x;
    if (bx < 768) {
        int n0 = (bx % 24) * 128, m0 = (bx / 24) * 128;
        gemm_body(g_xn_hi, g_xn_lo, g_wtok_hi, g_wtok_lo, g_th, g_tl,
                  3 * D_MOD, D_MOD, m0, n0, n0 < 2 * D_MOD, sm);
    } else {
        int bp = bx - 768;
        int n0 = (bp % 16) * 128, m0 = (bp / 16) * 128;
        gemm_body(g_pe_hi, g_pe_lo, g_wpos_hi, g_wpos_lo, g_ph, g_pl,
                  2 * D_MOD, D_MOD, m0, n0, true, sm);
    }
}

// ---------------------------------------------------------------------------
// Tensor-core flash attention, occupancy-2 version.
// CTA: 128 threads / 4 warps / 64 q rows. Q (hi/lo) held in REGISTERS.
// de=128 = [tok(64);pos(64)], QK 3-pass, PV 1-pass, online softmax.
// ---------------------------------------------------------------------------
#define QROW 272              // 128 halves + 8 pad, bytes
#define KROW 272
#define VROW 144              // 64 halves + 8 pad
#define KBYTES (64 * KROW)    // 17408
#define VBYTES (64 * VROW)    // 9216
#define STG (2 * KBYTES + VBYTES + 768)   // K hi/lo, V hi, bias = 44800
#define FL_SMEM (2 * STG)                 // 89600 -> 2 CTAs/SM

__device__ __forceinline__ void fl_prefetch_tile(uint32_t sb, const float* bias_table,
                                                 int b, int h, int hc, int q0, int k0,
                                                 int s, int tid) {
    const uint32_t kb = sb + s * STG;
    const size_t rb = ((size_t)b * S_LEN + k0) * 3072;
#pragma unroll
    for (int it = 0; it < 8; it++) {
        int e = tid + (it << 7);          // 0..1023
        int k = e >> 4, c = e & 15;
        uint32_t dst = kb + k * KROW + c * 16;
        if (c < 8) {
            size_t so = rb + (size_t)k * 3072 + hc + c * 8;
            cp_async16(dst, g_th + so);
            cp_async16(dst + KBYTES, g_tl + so);
        } else {
            size_t so = (size_t)(k0 + k) * 2048 + hc + (c - 8) * 8;
            cp_async16(dst, g_ph + so);
            cp_async16(dst + KBYTES, g_pl + so);
        }
    }
#pragma unroll
    for (int it = 0; it < 4; it++) {
        int e = tid + (it << 7);          // 0..511
        int k = e >> 3, c = e & 7;
        size_t so = rb + (size_t)k * 3072 + 2048 + hc + c * 8;
        cp_async16(kb + 2 * KBYTES + k * VROW + c * 16, g_th + so);
    }
    {
        int rel = k0 - q0 + MAXLEN - 63 + tid;   // tid 0..127, need [0,126]
        rel = rel > 2047 ? 2047 : rel;
        cp_async4(kb + 2 * KBYTES + VBYTES + tid * 4, bias_table + rel * N_H + h);
    }
}

__global__ void __launch_bounds__(128, 2) flash_kernel(const float* __restrict__ bias_table,
                                                       float* __restrict__ out) {
    extern __shared__ char sm[];
    const uint32_t sb = smem_u32(sm);
    const int tid = threadIdx.x, lane = tid & 31, wid = tid >> 5;  // wid 0..3
    const int lj = lane >> 3, lr = lane & 7;
    const int b = blockIdx.z, h = blockIdx.y, q0 = blockIdx.x * 64;
    const int hc = h * 64;
    const int m0w = wid * 16;

    // --- stage Q through smem (hi -> stage0 area, lo -> stage1 area), then to regs ---
    {
        const size_t rb = ((size_t)b * S_LEN + q0) * 3072;
#pragma unroll
        for (int it = 0; it < 8; it++) {
            int e = tid + (it << 7);          // 0..1023
            int q = e >> 4, c = e & 15;
            uint32_t dst = sb + q * QROW + c * 16;
            if (c < 8) {
                size_t so = rb + (size_t)q * 3072 + 1024 + hc + c * 8;
                cp_async16(dst, g_th + so);
                cp_async16(dst + STG, g_tl + so);
            } else {
                size_t so = (size_t)(q0 + q) * 2048 + 1024 + hc + (c - 8) * 8;
                cp_async16(dst, g_ph + so);
                cp_async16(dst + STG, g_pl + so);
            }
        }
        CP_COMMIT();
        CP_WAIT(0);
        __syncthreads();
    }
    uint32_t qh[8][4], qlo[8][4];
#pragma unroll
    for (int dk = 0; dk < 8; dk++) {
        uint32_t qa = sb + (m0w + (lj & 1) * 8 + lr) * QROW + (dk * 16 + (lj >> 1) * 8) * 2;
        ldm_x4(qh[dk], qa);
        ldm_x4(qlo[dk], qa + STG);
    }
    __syncthreads();   // all Q reads done before K prefetch overwrites

    fl_prefetch_tile(sb, bias_table, b, h, hc, q0, 0, 0, tid);
    CP_COMMIT();

    float O[8][4];
#pragma unroll
    for (int i = 0; i < 8; i++)
#pragma unroll
        for (int j = 0; j < 4; j++) O[i][j] = 0.f;
    float m0 = -INFINITY, m1 = -INFINITY, l0 = 0.f, l1 = 0.f;

    const float SCALE = 11.313708498984761f;
    const float LOG2E = 1.4426950408889634f;
    const int NT = S_LEN / 64;

    for (int kt = 0; kt < NT; kt++) {
        const int s = kt & 1;
        if (kt + 1 < NT) {
            fl_prefetch_tile(sb, bias_table, b, h, hc, q0, (kt + 1) * 64, s ^ 1, tid);
            CP_COMMIT();
            CP_WAIT(1);
        } else {
            CP_WAIT(0);
        }
        __syncthreads();

        const uint32_t khb = sb + s * STG;
        const uint32_t vhb = khb + 2 * KBYTES;
        const float* bias_s = (const float*)(sm + s * STG + 2 * KBYTES + VBYTES);

        // ---- S = Q K^T (hi/lo 3-pass), Q from registers ----
        float Sa[8][4];
#pragma unroll
        for (int i = 0; i < 8; i++)
#pragma unroll
            for (int j = 0; j < 4; j++) Sa[i][j] = 0.f;

#pragma unroll
        for (int dk = 0; dk < 8; dk++) {
#pragma unroll
            for (int ng = 0; ng < 4; ng++) {
                uint32_t bh[4], bl[4];
                uint32_t ka = khb + (ng * 16 + (lj >> 1) * 8 + lr) * KROW + (dk * 16 + (lj & 1) * 8) * 2;
                ldm_x4(bh, ka);
                ldm_x4(bl, ka + KBYTES);
                uint32_t b0[2] = {bh[0], bh[1]}, c0[2] = {bl[0], bl[1]};
                mma_f16(Sa[2 * ng], qh[dk], b0);
                mma_f16(Sa[2 * ng], qh[dk], c0);
                mma_f16(Sa[2 * ng], qlo[dk], b0);
                uint32_t b1[2] = {bh[2], bh[3]}, c1[2] = {bl[2], bl[3]};
                mma_f16(Sa[2 * ng + 1], qh[dk], b1);
                mma_f16(Sa[2 * ng + 1], qh[dk], c1);
                mma_f16(Sa[2 * ng + 1], qlo[dk], b1);
            }
        }

        // ---- scale + bias, online softmax, pack P (hi only) ----
        const int ql0 = m0w + (lane >> 2);
        float mx0 = -INFINITY, mx1 = -INFINITY;
#pragma unroll
        for (int tt = 0; tt < 8; tt++) {
            int ib = 63 + 8 * tt + 2 * (lane & 3) - ql0;
            float s0 = Sa[tt][0] * SCALE + bias_s[ib];
            float s1 = Sa[tt][1] * SCALE + bias_s[ib + 1];
            float s2 = Sa[tt][2] * SCALE + bias_s[ib - 8];
            float s3 = Sa[tt][3] * SCALE + bias_s[ib - 7];
            Sa[tt][0] = s0; Sa[tt][1] = s1; Sa[tt][2] = s2; Sa[tt][3] = s3;
            mx0 = fmaxf(mx0, fmaxf(s0, s1));
            mx1 = fmaxf(mx1, fmaxf(s2, s3));
        }
        mx0 = fmaxf(mx0, __shfl_xor_sync(0xffffffffu, mx0, 1));
        mx0 = fmaxf(mx0, __shfl_xor_sync(0xffffffffu, mx0, 2));
        mx1 = fmaxf(mx1, __shfl_xor_sync(0xffffffffu, mx1, 1));
        mx1 = fmaxf(mx1, __shfl_xor_sync(0xffffffffu, mx1, 2));
        float mn0 = fmaxf(m0, mx0), mn1 = fmaxf(m1, mx1);
        float a0 = exp2f((m0 - mn0) * LOG2E), a1 = exp2f((m1 - mn1) * LOG2E);
        m0 = mn0; m1 = mn1;

        uint32_t ph0[8], ph1[8];
        float r0 = 0.f, r1 = 0.f;
#pragma unroll
        for (int tt = 0; tt < 8; tt++) {
            float p0 = exp2f((Sa[tt][0] - m0) * LOG2E);
            float p1 = exp2f((Sa[tt][1] - m0) * LOG2E);
            float p2 = exp2f((Sa[tt][2] - m1) * LOG2E);
            float p3 = exp2f((Sa[tt][3] - m1) * LOG2E);
            r0 += p0 + p1; r1 += p2 + p3;
            ph0[tt] = h2u(__floats2half2_rn(p0, p1));
            ph1[tt] = h2u(__floats2half2_rn(p2, p3));
        }
        r0 += __shfl_xor_sync(0xffffffffu, r0, 1);
        r0 += __shfl_xor_sync(0xffffffffu, r0, 2);
        r1 += __shfl_xor_sync(0xffffffffu, r1, 1);
        r1 += __shfl_xor_sync(0xffffffffu, r1, 2);
        l0 = l0 * a0 + r0;
        l1 = l1 * a1 + r1;
#pragma unroll
        for (int dt = 0; dt < 8; dt++) {
            O[dt][0] *= a0; O[dt][1] *= a0; O[dt][2] *= a1; O[dt][3] *= a1;
        }

        // ---- O += P V (single pass), V via ldmatrix.trans ----
#pragma unroll
        for (int ck = 0; ck < 4; ck++) {
            uint32_t Ah[4] = {ph0[2 * ck], ph1[2 * ck], ph0[2 * ck + 1], ph1[2 * ck + 1]};
#pragma unroll
            for (int dg = 0; dg < 4; dg++) {
                uint32_t vh[4];
                uint32_t va = vhb + (ck * 16 + (lj & 1) * 8 + lr) * VROW + (dg * 16 + (lj >> 1) * 8) * 2;
                ldm_x4t(vh, va);
                uint32_t v0[2] = {vh[0], vh[1]};
                mma_f16(O[2 * dg], Ah, v0);
                uint32_t v1[2] = {vh[2], vh[3]};
                mma_f16(O[2 * dg + 1], Ah, v1);
            }
        }
        __syncthreads();
    }

    // ---- epilogue ----
    float inv0 = 1.f / l0, inv1 = 1.f / l1;
    size_t row = (size_t)b * S_LEN + q0 + m0w + (lane >> 2);
#pragma unroll
    for (int dt = 0; dt < 8; dt++) {
        int n = hc + dt * 8 + 2 * (lane & 3);
        *(float2*)(out + row * D_MOD + n) = make_float2(O[dt][0] * inv0, O[dt][1] * inv0);
        *(float2*)(out + (row + 8) * D_MOD + n) = make_float2(O[dt][2] * inv1, O[dt][3] * inv1);
    }
}

// ---------------------------------------------------------------------------
// Launch
// ---------------------------------------------------------------------------
extern "C" void kernel_launch(void* const* d_in, const int* in_sizes, int n_in,
                              void* d_out, int out_size) {
    const float* x          = (const float*)d_in[0];
    const float* gamma      = (const float*)d_in[1];
    const float* beta       = (const float*)d_in[2];
    const float* w_pos      = (const float*)d_in[3];
    const float* w_tok      = (const float*)d_in[4];
    const float* bias_table = (const float*)d_in[5];
    float* out = (float*)d_out;

    __half *wpos_hi, *wpos_lo, *wtok_hi, *wtok_lo;
    cudaGetSymbolAddress((void**)&wpos_hi, g_wpos_hi);
    cudaGetSymbolAddress((void**)&wpos_lo, g_wpos_lo);
    cudaGetSymbolAddress((void**)&wtok_hi, g_wtok_hi);
    cudaGetSymbolAddress((void**)&wtok_lo, g_wtok_lo);

    cudaFuncSetAttribute(gemm_merged, cudaFuncAttributeMaxDynamicSharedMemorySize, GEMM_SMEM);
    cudaFuncSetAttribute(flash_kernel, cudaFuncAttributeMaxDynamicSharedMemorySize, FL_SMEM);

    pe_kernel<<<S_LEN, 256>>>();
    split_kernel<<<(2 * D_MOD * D_MOD + 255) / 256, 256>>>(w_pos, wpos_hi, wpos_lo, 2 * D_MOD * D_MOD);
    split_kernel<<<(3 * D_MOD * D_MOD + 255) / 256, 256>>>(w_tok, wtok_hi, wtok_lo, 3 * D_MOD * D_MOD);
    ln_kernel<<<B_SZ * S_LEN, 256>>>(x, gamma, beta);
    // merged: tok = xn @ w_tok.T (768 blocks) + pos = pe @ w_pos.T (128 blocks)
    gemm_merged<<<896, 256, GEMM_SMEM>>>();
    // flash attention (tensor cores, occ 2)
    flash_kernel<<<dim3(S_LEN / 64, N_H, B_SZ), 128, FL_SMEM>>>(bias_table, out);
}

// round 8
// speedup vs baseline: 4.3653x; 1.0647x over previous
#include <cuda_runtime.h>
#include <cuda_fp16.h>
#include <math.h>
#include <stdint.h>

#define S_LEN 1024
#define D_MOD 1024
#define B_SZ 4
#define N_H 16
#define MAXLEN 1024

// ---------------------------------------------------------------------------
// Scratch (device globals — no allocations allowed)
// ---------------------------------------------------------------------------
__device__ __half g_pe_hi[S_LEN * D_MOD],        g_pe_lo[S_LEN * D_MOD];
__device__ __half g_wpos_hi[2 * D_MOD * D_MOD],  g_wpos_lo[2 * D_MOD * D_MOD];
__device__ __half g_xn_hi[B_SZ * S_LEN * D_MOD], g_xn_lo[B_SZ * S_LEN * D_MOD];
__device__ __half g_wtok_hi[3 * D_MOD * D_MOD],  g_wtok_lo[3 * D_MOD * D_MOD];
__device__ __half g_ph[S_LEN * 2 * D_MOD], g_pl[S_LEN * 2 * D_MOD];                      // pos
__device__ __half g_th[(size_t)B_SZ * S_LEN * 3 * D_MOD], g_tl[(size_t)B_SZ * S_LEN * 3 * D_MOD]; // tok
__device__ float  g_P0[(size_t)N_H * S_LEN * S_LEN];      // pos_attn*SCALE + bias, 67MB

// ---------------------------------------------------------------------------
// helpers
// ---------------------------------------------------------------------------
__device__ __forceinline__ uint32_t smem_u32(const void* p) {
    uint32_t a;
    asm("{ .reg .u64 t; cvta.to.shared.u64 t, %1; cvt.u32.u64 %0, t; }" : "=r"(a) : "l"(p));
    return a;
}
__device__ __forceinline__ void cp_async16(uint32_t dst, const void* src) {
    asm volatile("cp.async.cg.shared.global [%0], [%1], 16;" :: "r"(dst), "l"(src) : "memory");
}
__device__ __forceinline__ void cp_async4(uint32_t dst, const void* src) {
    asm volatile("cp.async.ca.shared.global [%0], [%1], 4;" :: "r"(dst), "l"(src) : "memory");
}
#define CP_COMMIT() asm volatile("cp.async.commit_group;" ::: "memory")
#define CP_WAIT(n)  asm volatile("cp.async.wait_group %0;" :: "n"(n) : "memory")

__device__ __forceinline__ void ldm_x4(uint32_t* r, uint32_t addr) {
    asm volatile("ldmatrix.sync.aligned.m8n8.x4.shared.b16 {%0,%1,%2,%3}, [%4];"
                 : "=r"(r[0]), "=r"(r[1]), "=r"(r[2]), "=r"(r[3]) : "r"(addr));
}
__device__ __forceinline__ void ldm_x4t(uint32_t* r, uint32_t addr) {
    asm volatile("ldmatrix.sync.aligned.m8n8.x4.trans.shared.b16 {%0,%1,%2,%3}, [%4];"
                 : "=r"(r[0]), "=r"(r[1]), "=r"(r[2]), "=r"(r[3]) : "r"(addr));
}
__device__ __forceinline__ void mma_f16(float* c, const uint32_t* a, const uint32_t* b) {
    asm volatile("mma.sync.aligned.m16n8k16.row.col.f32.f16.f16.f32 "
                 "{%0,%1,%2,%3}, {%4,%5,%6,%7}, {%8,%9}, {%0,%1,%2,%3};"
                 : "+f"(c[0]), "+f"(c[1]), "+f"(c[2]), "+f"(c[3])
                 : "r"(a[0]), "r"(a[1]), "r"(a[2]), "r"(a[3]), "r"(b[0]), "r"(b[1]));
}
__device__ __forceinline__ uint32_t h2u(__half2 h) { return *reinterpret_cast<uint32_t*>(&h); }

#define SCALE_F 11.313708498984761f   // sqrt(2*dh)

// ---------------------------------------------------------------------------
// PE (sinusoidal) -> fp16 hi/lo split
// ---------------------------------------------------------------------------
__global__ void pe_kernel() {
    int s = blockIdx.x;
    for (int d = threadIdx.x; d < D_MOD; d += blockDim.x) {
        int i = d >> 1;
        float div = expf((float)(2 * i) * (-9.210340371976184f / (float)D_MOD));
        float ang = (float)s * div;
        float v = (d & 1) ? cosf(ang) : sinf(ang);
        __half h = __float2half_rn(v);
        g_pe_hi[s * D_MOD + d] = h;
        g_pe_lo[s * D_MOD + d] = __float2half_rn(v - __half2float(h));
    }
}

// vectorized fp32 -> fp16 hi/lo split
__global__ void split4_kernel(const float4* __restrict__ src, uint32_t* __restrict__ hi,
                              uint32_t* __restrict__ lo, int n4) {
    int i = blockIdx.x * blockDim.x + threadIdx.x;
    if (i < n4) {
        float4 v = src[i];
        __half2 h0 = __floats2half2_rn(v.x, v.y);
        __half2 h1 = __floats2half2_rn(v.z, v.w);
        __half2 l0 = __floats2half2_rn(v.x - __low2float(h0), v.y - __high2float(h0));
        __half2 l1 = __floats2half2_rn(v.z - __low2float(h1), v.w - __high2float(h1));
        hi[2 * i] = h2u(h0); hi[2 * i + 1] = h2u(h1);
        lo[2 * i] = h2u(l0); lo[2 * i + 1] = h2u(l1);
    }
}

// ---------------------------------------------------------------------------
// LayerNorm -> fp16 hi/lo split
// ---------------------------------------------------------------------------
__global__ void __launch_bounds__(256) ln_kernel(const float* __restrict__ x,
                                                 const float* __restrict__ gamma,
                                                 const float* __restrict__ beta) {
    const int row = blockIdx.x;
    const float* xr = x + (size_t)row * D_MOD;
    const int t = threadIdx.x;
    const int lane = t & 31, wid = t >> 5;
    __shared__ float red[8];

    float v[4];
    float s = 0.f;
#pragma unroll
    for (int i = 0; i < 4; i++) { v[i] = xr[t + i * 256]; s += v[i]; }
#pragma unroll
    for (int o = 16; o > 0; o >>= 1) s += __shfl_xor_sync(0xffffffffu, s, o);
    if (lane == 0) red[wid] = s;
    __syncthreads();
    float tot = 0.f;
#pragma unroll
    for (int i = 0; i < 8; i++) tot += red[i];
    float mean = tot * (1.f / 1024.f);

    float sq = 0.f;
#pragma unroll
    for (int i = 0; i < 4; i++) { float d = v[i] - mean; sq += d * d; }
#pragma unroll
    for (int o = 16; o > 0; o >>= 1) sq += __shfl_xor_sync(0xffffffffu, sq, o);
    __syncthreads();
    if (lane == 0) red[wid] = sq;
    __syncthreads();
    float tot2 = 0.f;
#pragma unroll
    for (int i = 0; i < 8; i++) tot2 += red[i];
    float rstd = rsqrtf(tot2 * (1.f / 1024.f) + 1e-5f);

#pragma unroll
    for (int i = 0; i < 4; i++) {
        int c = t + i * 256;
        float y = (v[i] - mean) * rstd * gamma[c] + beta[c];
        __half h = __float2half_rn(y);
        g_xn_hi[(size_t)row * D_MOD + c] = h;
        g_xn_lo[(size_t)row * D_MOD + c] = __float2half_rn(y - __half2float(h));
    }
}

// ---------------------------------------------------------------------------
// mma.sync fp16x2-split NT GEMM body (device fn), merged launch for pos+tok
// ---------------------------------------------------------------------------
#define OPBUF 10240
#define GEMM_SMEM (8 * OPBUF)

__device__ __forceinline__ void gemm_body(
    const __half* __restrict__ Ahi, const __half* __restrict__ Alo,
    const __half* __restrict__ Bhi, const __half* __restrict__ Blo,
    __half* __restrict__ Chi, __half* __restrict__ Clo,
    int N, int K, int m0, int n0, bool full, char* sm)
{
    const uint32_t sb = smem_u32(sm);
    const int tid = threadIdx.x;
    const int lane = tid & 31, wid = tid >> 5;
    const int wm = wid >> 2, wn = wid & 3;

    float acc[4][4][4];
#pragma unroll
    for (int i = 0; i < 4; i++)
#pragma unroll
        for (int j = 0; j < 4; j++)
#pragma unroll
            for (int r = 0; r < 4; r++) acc[i][j][r] = 0.f;

    const __half* srcs[4] = {Ahi, Alo, Bhi, Blo};
    const int rows0[4] = {m0, m0, n0, n0};
    const int NCH = K >> 5;
    const int lj = lane >> 3, lr = lane & 7;

#pragma unroll
    for (int op = 0; op < 4; op++) {
        if (op == 1 && !full) continue;
#pragma unroll
        for (int it = 0; it < 2; it++) {
            int e = tid + (it << 8);
            int r = e >> 2, cs = e & 3;
            cp_async16(sb + op * OPBUF + r * 80 + cs * 16,
                       srcs[op] + (size_t)(rows0[op] + r) * K + (cs << 3));
        }
    }
    CP_COMMIT();

    for (int i = 0; i < NCH; i++) {
        const int s = i & 1;
        if (i + 1 < NCH) {
            const int s2 = s ^ 1, k0 = (i + 1) << 5;
#pragma unroll
            for (int op = 0; op < 4; op++) {
                if (op == 1 && !full) continue;
#pragma unroll
                for (int it = 0; it < 2; it++) {
                    int e = tid + (it << 8);
                    int r = e >> 2, cs = e & 3;
                    cp_async16(sb + (s2 * 4 + op) * OPBUF + r * 80 + cs * 16,
                               srcs[op] + (size_t)(rows0[op] + r) * K + k0 + (cs << 3));
                }
            }
            CP_COMMIT();
            CP_WAIT(1);
        } else {
            CP_WAIT(0);
        }
        __syncthreads();

        const uint32_t ah_b = sb + (s * 4 + 0) * OPBUF;
        const uint32_t al_b = sb + (s * 4 + 1) * OPBUF;
        const uint32_t bh_b = sb + (s * 4 + 2) * OPBUF;
        const uint32_t bl_b = sb + (s * 4 + 3) * OPBUF;

#pragma unroll
        for (int kk = 0; kk < 32; kk += 16) {
            uint32_t ah[4][4], al[4][4];
#pragma unroll
            for (int tm = 0; tm < 4; tm++) {
                int m = wm * 64 + tm * 16 + (lj & 1) * 8 + lr;
                int k = kk + (lj >> 1) * 8;
                ldm_x4(ah[tm], ah_b + m * 80 + k * 2);
                if (full) ldm_x4(al[tm], al_b + m * 80 + k * 2);
            }
            uint32_t bh[2][4], bl[2][4];
#pragma unroll
            for (int tn = 0; tn < 2; tn++) {
                int n = wn * 32 + tn * 16 + (lj >> 1) * 8 + lr;
                int k = kk + (lj & 1) * 8;
                ldm_x4(bh[tn], bh_b + n * 80 + k * 2);
                ldm_x4(bl[tn], bl_b + n * 80 + k * 2);
            }
#pragma unroll
            for (int tm = 0; tm < 4; tm++)
#pragma unroll
                for (int t8 = 0; t8 < 4; t8++) {
                    uint32_t bhr[2] = {bh[t8 >> 1][2 * (t8 & 1)], bh[t8 >> 1][2 * (t8 & 1) + 1]};
                    uint32_t blr[2] = {bl[t8 >> 1][2 * (t8 & 1)], bl[t8 >> 1][2 * (t8 & 1) + 1]};
                    mma_f16(acc[tm][t8], ah[tm], bhr);
                    mma_f16(acc[tm][t8], ah[tm], blr);
                    if (full) mma_f16(acc[tm][t8], al[tm], bhr);
                }
        }
        __syncthreads();
    }

#pragma unroll
    for (int tm = 0; tm < 4; tm++) {
        int m = m0 + wm * 64 + tm * 16 + (lane >> 2);
#pragma unroll
        for (int t8 = 0; t8 < 4; t8++) {
            int n = n0 + wn * 32 + t8 * 8 + 2 * (lane & 3);
            float v0 = acc[tm][t8][0], v1 = acc[tm][t8][1];
            float v2 = acc[tm][t8][2], v3 = acc[tm][t8][3];
            __half2 h01 = __floats2half2_rn(v0, v1);
            __half2 h23 = __floats2half2_rn(v2, v3);
            *(__half2*)(Chi + (size_t)m * N + n) = h01;
            *(__half2*)(Chi + (size_t)(m + 8) * N + n) = h23;
            if (full) {
                __half2 l01 = __floats2half2_rn(v0 - __low2float(h01), v1 - __high2float(h01));
                __half2 l23 = __floats2half2_rn(v2 - __low2float(h23), v3 - __high2float(h23));
                *(__half2*)(Clo + (size_t)m * N + n) = l01;
                *(__half2*)(Clo + (size_t)(m + 8) * N + n) = l23;
            }
        }
    }
}

// merged launch: blocks [0,768) = tok (24 x 32), blocks [768,896) = pos (16 x 8)
__global__ void __launch_bounds__(256) gemm_merged() {
    extern __shared__ char sm[];
    int bx = blockIdx.x;
    if (bx < 768) {
        int n0 = (bx % 24) * 128, m0 = (bx / 24) * 128;
        gemm_body(g_xn_hi, g_xn_lo, g_wtok_hi, g_wtok_lo, g_th, g_tl,
                  3 * D_MOD, D_MOD, m0, n0, n0 < 2 * D_MOD, sm);
    } else {
        int bp = bx - 768;
        int n0 = (bp % 16) * 128, m0 = (bp / 16) * 128;
        gemm_body(g_pe_hi, g_pe_lo, g_wpos_hi, g_wpos_lo, g_ph, g_pl,
                  2 * D_MOD, D_MOD, m0, n0, true, sm);
    }
}

// ---------------------------------------------------------------------------
// P0[h,q,k] = (pos_q[q,h,:] . pos_k[k,h,:]) * SCALE + bias_table[k-q+1024, h]
// CTA: 128q x 128k per head. K-dim 64, single shot. 256 threads, 8 warps 64x32.
// ---------------------------------------------------------------------------
#define PA_SMEM (4 * 18432 + 1024)   // A hi/lo + B hi/lo (128x144 each) + bias = 74752

__global__ void __launch_bounds__(256) posattn_kernel(const float* __restrict__ bias_table) {
    extern __shared__ char sm[];
    const uint32_t sb = smem_u32(sm);
    const int tid = threadIdx.x, lane = tid & 31, wid = tid >> 5;
    const int wm = wid >> 2, wn = wid & 3;
    const int h = blockIdx.z, q0 = blockIdx.y * 128, k0 = blockIdx.x * 128;
    const int hc = h * 64;
    const int lj = lane >> 3, lr = lane & 7;

    // load A = pos_q (rows q0..+128, col 1024+hc), B = pos_k (rows k0..+128, col hc)
#pragma unroll
    for (int it = 0; it < 4; it++) {
        int e = tid + (it << 8);
        int r = e >> 3, c = e & 7;
        size_t qa = (size_t)(q0 + r) * 2048 + 1024 + hc + c * 8;
        size_t ka = (size_t)(k0 + r) * 2048 + hc + c * 8;
        uint32_t o = r * 144 + c * 16;
        cp_async16(sb + o, g_ph + qa);
        cp_async16(sb + 18432 + o, g_pl + qa);
        cp_async16(sb + 36864 + o, g_ph + ka);
        cp_async16(sb + 55296 + o, g_pl + ka);
    }
    {
        int rel = k0 - q0 + 897 + tid;   // need idx 0..254
        rel = rel < 0 ? 0 : (rel > 2047 ? 2047 : rel);
        cp_async4(sb + 73728 + tid * 4, bias_table + rel * N_H + h);
    }
    CP_COMMIT();
    CP_WAIT(0);
    __syncthreads();

    float acc[4][4][4];
#pragma unroll
    for (int i = 0; i < 4; i++)
#pragma unroll
        for (int j = 0; j < 4; j++)
#pragma unroll
            for (int r = 0; r < 4; r++) acc[i][j][r] = 0.f;

#pragma unroll
    for (int kk = 0; kk < 4; kk++) {
        uint32_t ah[4][4], al[4][4];
#pragma unroll
        for (int tm = 0; tm < 4; tm++) {
            int m = wm * 64 + tm * 16 + (lj & 1) * 8 + lr;
            int k = kk * 16 + (lj >> 1) * 8;
            ldm_x4(ah[tm], sb + m * 144 + k * 2);
            ldm_x4(al[tm], sb + 18432 + m * 144 + k * 2);
        }
        uint32_t bh[2][4], bl[2][4];
#pragma unroll
        for (int tn = 0; tn < 2; tn++) {
            int n = wn * 32 + tn * 16 + (lj >> 1) * 8 + lr;
            int k = kk * 16 + (lj & 1) * 8;
            ldm_x4(bh[tn], sb + 36864 + n * 144 + k * 2);
            ldm_x4(bl[tn], sb + 55296 + n * 144 + k * 2);
        }
#pragma unroll
        for (int tm = 0; tm < 4; tm++)
#pragma unroll
            for (int t8 = 0; t8 < 4; t8++) {
                uint32_t bhr[2] = {bh[t8 >> 1][2 * (t8 & 1)], bh[t8 >> 1][2 * (t8 & 1) + 1]};
                uint32_t blr[2] = {bl[t8 >> 1][2 * (t8 & 1)], bl[t8 >> 1][2 * (t8 & 1) + 1]};
                mma_f16(acc[tm][t8], ah[tm], bhr);
                mma_f16(acc[tm][t8], ah[tm], blr);
                mma_f16(acc[tm][t8], al[tm], bhr);
            }
    }

    const float* bias_s = (const float*)(sm + 73728);
    float* P0b = g_P0 + ((size_t)h << 20);
#pragma unroll
    for (int tm = 0; tm < 4; tm++) {
        int q = wm * 64 + tm * 16 + (lane >> 2);
#pragma unroll
        for (int t8 = 0; t8 < 4; t8++) {
            int k = wn * 32 + t8 * 8 + 2 * (lane & 3);
            int idx = k - q + 127;
            float o0 = acc[tm][t8][0] * SCALE_F + bias_s[idx];
            float o1 = acc[tm][t8][1] * SCALE_F + bias_s[idx + 1];
            float o2 = acc[tm][t8][2] * SCALE_F + bias_s[idx - 8];
            float o3 = acc[tm][t8][3] * SCALE_F + bias_s[idx - 7];
            *(float2*)(P0b + (size_t)(q0 + q) * 1024 + k0 + k) = make_float2(o0, o1);
            *(float2*)(P0b + (size_t)(q0 + q + 8) * 1024 + k0 + k) = make_float2(o2, o3);
        }
    }
}

// ---------------------------------------------------------------------------
// Tensor-core flash attention, de=64 (tok only), P0 carries pos+bias.
// CTA: 128 threads / 4 warps / 64 q rows, occ 2. QK 3-pass, PV 1-pass.
// ---------------------------------------------------------------------------
#define KROW2 144             // 64 halves + 8 pad
#define KB2 9216              // 64 * 144
#define P0ROW 272             // 64 floats + 4 pad
#define STG (2 * KB2 + KB2 + 64 * P0ROW)   // K hi/lo + V hi + P0 = 45056
#define FL_SMEM (2 * STG)                  // 90112 -> 2 CTAs/SM

__device__ __forceinline__ void fl_prefetch_tile(uint32_t sb, int b, int h, int hc,
                                                 int q0, int k0, int s, int tid) {
    const uint32_t kb = sb + s * STG;
    const size_t rb = ((size_t)b * S_LEN + k0) * 3072;
#pragma unroll
    for (int it = 0; it < 4; it++) {
        int e = tid + (it << 7);          // 0..511
        int k = e >> 3, c = e & 7;
        size_t so = rb + (size_t)k * 3072 + hc + c * 8;
        uint32_t o = k * KROW2 + c * 16;
        cp_async16(kb + o, g_th + so);
        cp_async16(kb + KB2 + o, g_tl + so);
        size_t sv = rb + (size_t)k * 3072 + 2048 + hc + c * 8;
        cp_async16(kb + 2 * KB2 + o, g_th + sv);
    }
    const float* p0src = g_P0 + ((size_t)h << 20) + (size_t)q0 * 1024 + k0;
#pragma unroll
    for (int it = 0; it < 8; it++) {
        int e = tid + (it << 7);          // 0..1023
        int r = e >> 4, c = e & 15;
        cp_async16(kb + 3 * KB2 + r * P0ROW + c * 16, p0src + (size_t)r * 1024 + c * 4);
    }
}

__global__ void __launch_bounds__(128, 2) flash_kernel(float* __restrict__ out) {
    extern __shared__ char sm[];
    const uint32_t sb = smem_u32(sm);
    const int tid = threadIdx.x, lane = tid & 31, wid = tid >> 5;  // wid 0..3
    const int lj = lane >> 3, lr = lane & 7;
    const int b = blockIdx.z, h = blockIdx.y, q0 = blockIdx.x * 64;
    const int hc = h * 64;
    const int m0w = wid * 16;

    // --- stage Q (tok only, hi/lo) through smem, then to regs ---
    {
        const size_t rb = ((size_t)b * S_LEN + q0) * 3072;
#pragma unroll
        for (int it = 0; it < 4; it++) {
            int e = tid + (it << 7);          // 0..511
            int q = e >> 3, c = e & 7;
            size_t so = rb + (size_t)q * 3072 + 1024 + hc + c * 8;
            cp_async16(sb + q * KROW2 + c * 16, g_th + so);
            cp_async16(sb + STG + q * KROW2 + c * 16, g_tl + so);
        }
        CP_COMMIT();
        CP_WAIT(0);
        __syncthreads();
    }
    uint32_t qh[4][4], qlo[4][4];
#pragma unroll
    for (int dk = 0; dk < 4; dk++) {
        uint32_t qa = sb + (m0w + (lj & 1) * 8 + lr) * KROW2 + (dk * 16 + (lj >> 1) * 8) * 2;
        ldm_x4(qh[dk], qa);
        ldm_x4(qlo[dk], qa + STG);
    }
    __syncthreads();   // all Q reads done before K prefetch overwrites

    fl_prefetch_tile(sb, b, h, hc, q0, 0, 0, tid);
    CP_COMMIT();

    float O[8][4];
#pragma unroll
    for (int i = 0; i < 8; i++)
#pragma unroll
        for (int j = 0; j < 4; j++) O[i][j] = 0.f;
    float m0 = -INFINITY, m1 = -INFINITY, l0 = 0.f, l1 = 0.f;

    const float LOG2E = 1.4426950408889634f;
    const int NT = S_LEN / 64;

    for (int kt = 0; kt < NT; kt++) {
        const int s = kt & 1;
        if (kt + 1 < NT) {
            fl_prefetch_tile(sb, b, h, hc, q0, (kt + 1) * 64, s ^ 1, tid);
            CP_COMMIT();
            CP_WAIT(1);
        } else {
            CP_WAIT(0);
        }
        __syncthreads();

        const uint32_t khb = sb + s * STG;
        const uint32_t vhb = khb + 2 * KB2;
        const char* p0s = sm + s * STG + 3 * KB2;

        // ---- S = Q K^T (hi/lo 3-pass, de=64), Q from registers ----
        float Sa[8][4];
#pragma unroll
        for (int i = 0; i < 8; i++)
#pragma unroll
            for (int j = 0; j < 4; j++) Sa[i][j] = 0.f;

#pragma unroll
        for (int dk = 0; dk < 4; dk++) {
#pragma unroll
            for (int ng = 0; ng < 4; ng++) {
                uint32_t bh[4], bl[4];
                uint32_t ka = khb + (ng * 16 + (lj >> 1) * 8 + lr) * KROW2 + (dk * 16 + (lj & 1) * 8) * 2;
                ldm_x4(bh, ka);
                ldm_x4(bl, ka + KB2);
                uint32_t b0[2] = {bh[0], bh[1]}, c0[2] = {bl[0], bl[1]};
                mma_f16(Sa[2 * ng], qh[dk], b0);
                mma_f16(Sa[2 * ng], qh[dk], c0);
                mma_f16(Sa[2 * ng], qlo[dk], b0);
                uint32_t b1[2] = {bh[2], bh[3]}, c1[2] = {bl[2], bl[3]};
                mma_f16(Sa[2 * ng + 1], qh[dk], b1);
                mma_f16(Sa[2 * ng + 1], qh[dk], c1);
                mma_f16(Sa[2 * ng + 1], qlo[dk], b1);
            }
        }

        // ---- add P0 (pos+bias), online softmax, pack P (hi only) ----
        const int qr = m0w + (lane >> 2);
        float mx0 = -INFINITY, mx1 = -INFINITY;
#pragma unroll
        for (int tt = 0; tt < 8; tt++) {
            int kl = 8 * tt + 2 * (lane & 3);
            float2 b0 = *(const float2*)(p0s + qr * P0ROW + kl * 4);
            float2 b1 = *(const float2*)(p0s + (qr + 8) * P0ROW + kl * 4);
            float s0 = Sa[tt][0] * SCALE_F + b0.x;
            float s1 = Sa[tt][1] * SCALE_F + b0.y;
            float s2 = Sa[tt][2] * SCALE_F + b1.x;
            float s3 = Sa[tt][3] * SCALE_F + b1.y;
            Sa[tt][0] = s0; Sa[tt][1] = s1; Sa[tt][2] = s2; Sa[tt][3] = s3;
            mx0 = fmaxf(mx0, fmaxf(s0, s1));
            mx1 = fmaxf(mx1, fmaxf(s2, s3));
        }
        mx0 = fmaxf(mx0, __shfl_xor_sync(0xffffffffu, mx0, 1));
        mx0 = fmaxf(mx0, __shfl_xor_sync(0xffffffffu, mx0, 2));
        mx1 = fmaxf(mx1, __shfl_xor_sync(0xffffffffu, mx1, 1));
        mx1 = fmaxf(mx1, __shfl_xor_sync(0xffffffffu, mx1, 2));
        float mn0 = fmaxf(m0, mx0), mn1 = fmaxf(m1, mx1);
        float a0 = exp2f((m0 - mn0) * LOG2E), a1 = exp2f((m1 - mn1) * LOG2E);
        m0 = mn0; m1 = mn1;

        uint32_t ph0[8], ph1[8];
        float r0 = 0.f, r1 = 0.f;
#pragma unroll
        for (int tt = 0; tt < 8; tt++) {
            float p0 = exp2f((Sa[tt][0] - m0) * LOG2E);
            float p1 = exp2f((Sa[tt][1] - m0) * LOG2E);
            float p2 = exp2f((Sa[tt][2] - m1) * LOG2E);
            float p3 = exp2f((Sa[tt][3] - m1) * LOG2E);
            r0 += p0 + p1; r1 += p2 + p3;
            ph0[tt] = h2u(__floats2half2_rn(p0, p1));
            ph1[tt] = h2u(__floats2half2_rn(p2, p3));
        }
        r0 += __shfl_xor_sync(0xffffffffu, r0, 1);
        r0 += __shfl_xor_sync(0xffffffffu, r0, 2);
        r1 += __shfl_xor_sync(0xffffffffu, r1, 1);
        r1 += __shfl_xor_sync(0xffffffffu, r1, 2);
        l0 = l0 * a0 + r0;
        l1 = l1 * a1 + r1;
#pragma unroll
        for (int dt = 0; dt < 8; dt++) {
            O[dt][0] *= a0; O[dt][1] *= a0; O[dt][2] *= a1; O[dt][3] *= a1;
        }

        // ---- O += P V (single pass), V via ldmatrix.trans ----
#pragma unroll
        for (int ck = 0; ck < 4; ck++) {
            uint32_t Ah[4] = {ph0[2 * ck], ph1[2 * ck], ph0[2 * ck + 1], ph1[2 * ck + 1]};
#pragma unroll
            for (int dg = 0; dg < 4; dg++) {
                uint32_t vh[4];
                uint32_t va = vhb + (ck * 16 + (lj & 1) * 8 + lr) * KROW2 + (dg * 16 + (lj >> 1) * 8) * 2;
                ldm_x4t(vh, va);
                uint32_t v0[2] = {vh[0], vh[1]};
                mma_f16(O[2 * dg], Ah, v0);
                uint32_t v1[2] = {vh[2], vh[3]};
                mma_f16(O[2 * dg + 1], Ah, v1);
            }
        }
        __syncthreads();
    }

    // ---- epilogue ----
    float inv0 = 1.f / l0, inv1 = 1.f / l1;
    size_t row = (size_t)b * S_LEN + q0 + m0w + (lane >> 2);
#pragma unroll
    for (int dt = 0; dt < 8; dt++) {
        int n = hc + dt * 8 + 2 * (lane & 3);
        *(float2*)(out + row * D_MOD + n) = make_float2(O[dt][0] * inv0, O[dt][1] * inv0);
        *(float2*)(out + (row + 8) * D_MOD + n) = make_float2(O[dt][2] * inv1, O[dt][3] * inv1);
    }
}

// ---------------------------------------------------------------------------
// Launch
// ---------------------------------------------------------------------------
extern "C" void kernel_launch(void* const* d_in, const int* in_sizes, int n_in,
                              void* d_out, int out_size) {
    const float* x          = (const float*)d_in[0];
    const float* gamma      = (const float*)d_in[1];
    const float* beta       = (const float*)d_in[2];
    const float* w_pos      = (const float*)d_in[3];
    const float* w_tok      = (const float*)d_in[4];
    const float* bias_table = (const float*)d_in[5];
    float* out = (float*)d_out;

    __half *wpos_hi, *wpos_lo, *wtok_hi, *wtok_lo;
    cudaGetSymbolAddress((void**)&wpos_hi, g_wpos_hi);
    cudaGetSymbolAddress((void**)&wpos_lo, g_wpos_lo);
    cudaGetSymbolAddress((void**)&wtok_hi, g_wtok_hi);
    cudaGetSymbolAddress((void**)&wtok_lo, g_wtok_lo);

    cudaFuncSetAttribute(gemm_merged, cudaFuncAttributeMaxDynamicSharedMemorySize, GEMM_SMEM);
    cudaFuncSetAttribute(posattn_kernel, cudaFuncAttributeMaxDynamicSharedMemorySize, PA_SMEM);
    cudaFuncSetAttribute(flash_kernel, cudaFuncAttributeMaxDynamicSharedMemorySize, FL_SMEM);

    pe_kernel<<<S_LEN, 256>>>();
    split4_kernel<<<(2 * D_MOD * D_MOD / 4 + 255) / 256, 256>>>(
        (const float4*)w_pos, (uint32_t*)wpos_hi, (uint32_t*)wpos_lo, 2 * D_MOD * D_MOD / 4);
    split4_kernel<<<(3 * D_MOD * D_MOD / 4 + 255) / 256, 256>>>(
        (const float4*)w_tok, (uint32_t*)wtok_hi, (uint32_t*)wtok_lo, 3 * D_MOD * D_MOD / 4);
    ln_kernel<<<B_SZ * S_LEN, 256>>>(x, gamma, beta);
    // merged: tok = xn @ w_tok.T (768 blocks) + pos = pe @ w_pos.T (128 blocks)
    gemm_merged<<<896, 256, GEMM_SMEM>>>();
    // P0 = pos_attn*SCALE + bias (batch-independent)
    posattn_kernel<<<dim3(8, 8, 16), 256, PA_SMEM>>>(bias_table);
    // flash attention (de=64 tok-only, tensor cores, occ 2)
    flash_kernel<<<dim3(S_LEN / 64, N_H, B_SZ), 128, FL_SMEM>>>(out);
}